// round 1
// baseline (speedup 1.0000x reference)
#include <cuda_runtime.h>
#include <math.h>
#include <cstdint>

// ---------------------------------------------------------------------------
// Problem constants (B=1)
// ---------------------------------------------------------------------------
#define CT 2048      // tokens
#define CD 2048      // model dim
#define CH 32        // q heads
#define CHK 8        // kv heads
#define CDH 64       // head dim
#define CINTER 8192  // ffn inner
// low ranks: q/k/v = 32, o/ffn = 512

// ---------------------------------------------------------------------------
// Static device scratch (allocation-free rule: __device__ globals)
// ---------------------------------------------------------------------------
struct Scratch {
  float x[CT * CD];            // rmsnorm output (reused for x2)
  float Pq[CT * (CH * 32)];    // (T, 1024)
  float Pk[CT * (CHK * 32)];   // (T, 256)
  float Pv[CT * (CHK * 32)];
  float q[CH * CT * CDH];      // (H, T, 64) roped
  float k[CHK * CT * CDH];
  float v[CHK * CT * CDH];
  float attn[CT * CD];         // (T, D) head-merged attention out
  float Po[CT * 512];
  float h[CT * CD];            // residual 1
  float Pg[CT * 512];
  float Pu[CT * 512];
  float gate[CT * CINTER];     // also holds act after silu
  float up[CT * CINTER];
  float Pd[CT * 512];
};
__device__ Scratch g_scratch;

// ---------------------------------------------------------------------------
// RMSNorm: one block per row of 2048
// ---------------------------------------------------------------------------
__global__ void rmsnorm_kernel(const float* __restrict__ in,
                               const float* __restrict__ w,
                               float* __restrict__ out) {
  const int t = blockIdx.x;
  const float* row = in + (size_t)t * CD;
  float ss = 0.f;
  for (int i = threadIdx.x; i < CD; i += 256) {
    float v = row[i];
    ss += v * v;
  }
  __shared__ float red[8];
#pragma unroll
  for (int o = 16; o > 0; o >>= 1) ss += __shfl_xor_sync(0xffffffffu, ss, o);
  if ((threadIdx.x & 31) == 0) red[threadIdx.x >> 5] = ss;
  __syncthreads();
  if (threadIdx.x == 0) {
    float v = 0.f;
#pragma unroll
    for (int i = 0; i < 8; i++) v += red[i];
    red[0] = v;
  }
  __syncthreads();
  const float inv = rsqrtf(red[0] * (1.0f / CD) + 1e-5f);
  for (int i = threadIdx.x; i < CD; i += 256)
    out[(size_t)t * CD + i] = row[i] * inv * w[i];
}

// ---------------------------------------------------------------------------
// SGEMM (NT): C[M,N] = A[M,K] * B[N,K]^T (+ res).  M,N mult of 128, K mult of 8.
// 128x128 tile, 8x8 microtile, 256 threads.
// ---------------------------------------------------------------------------
__global__ __launch_bounds__(256, 2) void sgemm_nt(
    const float* __restrict__ A, const float* __restrict__ B,
    const float* __restrict__ res, float* __restrict__ C,
    int N, int K) {
  __shared__ float As[8][128];
  __shared__ float Bs[8][128];
  const int bm = blockIdx.y * 128;
  const int bn = blockIdx.x * 128;
  const int tid = threadIdx.x;
  const int lr = tid >> 1;
  const int lc = (tid & 1) * 4;
  const int tx = tid & 15;
  const int ty = tid >> 4;
  const float* Ap = A + (size_t)(bm + lr) * K + lc;
  const float* Bp = B + (size_t)(bn + lr) * K + lc;
  float acc[8][8];
#pragma unroll
  for (int i = 0; i < 8; i++)
#pragma unroll
    for (int j = 0; j < 8; j++) acc[i][j] = 0.f;

  for (int k0 = 0; k0 < K; k0 += 8) {
    const float4 a = *(const float4*)(Ap + k0);
    const float4 b = *(const float4*)(Bp + k0);
    __syncthreads();
    As[lc + 0][lr] = a.x; As[lc + 1][lr] = a.y;
    As[lc + 2][lr] = a.z; As[lc + 3][lr] = a.w;
    Bs[lc + 0][lr] = b.x; Bs[lc + 1][lr] = b.y;
    Bs[lc + 2][lr] = b.z; Bs[lc + 3][lr] = b.w;
    __syncthreads();
#pragma unroll
    for (int kk = 0; kk < 8; kk++) {
      const float4 a0 = *(const float4*)&As[kk][ty * 8];
      const float4 a1 = *(const float4*)&As[kk][ty * 8 + 4];
      const float4 b0 = *(const float4*)&Bs[kk][tx * 8];
      const float4 b1 = *(const float4*)&Bs[kk][tx * 8 + 4];
      const float ar[8] = {a0.x, a0.y, a0.z, a0.w, a1.x, a1.y, a1.z, a1.w};
      const float br[8] = {b0.x, b0.y, b0.z, b0.w, b1.x, b1.y, b1.z, b1.w};
#pragma unroll
      for (int i = 0; i < 8; i++)
#pragma unroll
        for (int j = 0; j < 8; j++) acc[i][j] = fmaf(ar[i], br[j], acc[i][j]);
    }
  }

#pragma unroll
  for (int i = 0; i < 8; i++) {
    const int r = bm + ty * 8 + i;
#pragma unroll
    for (int j = 0; j < 8; j += 4) {
      const int c = bn + tx * 8 + j;
      float4 v = make_float4(acc[i][j], acc[i][j + 1], acc[i][j + 2], acc[i][j + 3]);
      if (res) {
        const float4 rv = *(const float4*)&res[(size_t)r * N + c];
        v.x += rv.x; v.y += rv.y; v.z += rv.z; v.w += rv.w;
      }
      *(float4*)&C[(size_t)r * N + c] = v;
    }
  }
}

// ---------------------------------------------------------------------------
// Per-head Us projection (rank 32 -> head dim 64) with optional fused RoPE.
// grid: (T/8, nheads), block: (32, 8).  thread = (half-dim index, local token)
// out layout: [head][t][d]
// ---------------------------------------------------------------------------
__global__ void proj_us_rope(const float* __restrict__ P,
                             const float* __restrict__ Us,
                             float* __restrict__ out, int nheads, int doRope) {
  const int hh = blockIdx.y;
  const int tt = threadIdx.y;
  const int t = blockIdx.x * 8 + tt;
  const int dh = threadIdx.x;  // 0..31
  __shared__ float sUs[64][32];
  __shared__ float sP[8][32];
  const int tid = tt * 32 + dh;
  const float* UsH = Us + (size_t)hh * 64 * 32;
#pragma unroll
  for (int i = tid; i < 64 * 32; i += 256) sUs[i >> 5][i & 31] = UsH[i];
  sP[tt][dh] = P[(size_t)t * (nheads * 32) + hh * 32 + dh];
  __syncthreads();
  float x1 = 0.f, x2 = 0.f;
#pragma unroll
  for (int r = 0; r < 32; r++) {
    const float p = sP[tt][r];
    x1 = fmaf(p, sUs[dh][r], x1);
    x2 = fmaf(p, sUs[dh + 32][r], x2);
  }
  float o1 = x1, o2 = x2;
  if (doRope) {
    // inv_freq = 10000^(-dh/32) = 2^(-dh * log2(10000)/32)
    const float invf = exp2f(-0.41524101186092028f * (float)dh);
    const float ang = (float)t * invf;
    float sn, cs;
    sincosf(ang, &sn, &cs);
    o1 = x1 * cs - x2 * sn;
    o2 = x2 * cs + x1 * sn;
  }
  const size_t base = ((size_t)hh * CT + t) * CDH;
  out[base + dh] = o1;
  out[base + dh + 32] = o2;
}

// ---------------------------------------------------------------------------
// Causal flash attention, fp32. 64x64 tiles, Dh=64, GQA rep 4.
// grid: (T/64, H). block: 256 threads, 4x4 fragments.
// Writes attn in merged (t, h*64+d) layout.
// ---------------------------------------------------------------------------
#define FA_SMEM_FLOATS (4096 * 3 + 64 * 68 + 64 * 3 + 64 * 16)
__global__ __launch_bounds__(256) void flash_attn(
    const float* __restrict__ Q, const float* __restrict__ Kg,
    const float* __restrict__ Vg, float* __restrict__ Og) {
  extern __shared__ float sm[];
  float* Qt = sm;                 // [d][r]  4096
  float* Kt = sm + 4096;          // [d][c]  4096
  float* Vs = sm + 8192;          // [kk][d] 4096
  float* Ps = sm + 12288;         // [kk][r] stride 68
  float* mrow = Ps + 64 * 68;
  float* lrow = mrow + 64;
  float* arow = lrow + 64;
  float* red = arow + 64;         // [64][16]

  const int qb = blockIdx.x, hh = blockIdx.y, hk = hh >> 2;
  const int tid = threadIdx.x;
  const int tx = tid & 15, ty = tid >> 4;
  const int r0 = ty * 4, c0 = tx * 4;
  const int ldr = tid >> 2;
  const int ldd = (tid & 3) * 16;

  {
    const float* qg = Q + ((size_t)hh * CT + qb * 64 + ldr) * 64 + ldd;
#pragma unroll
    for (int j = 0; j < 16; j += 4) {
      const float4 a = *(const float4*)(qg + j);
      Qt[(ldd + j + 0) * 64 + ldr] = a.x;
      Qt[(ldd + j + 1) * 64 + ldr] = a.y;
      Qt[(ldd + j + 2) * 64 + ldr] = a.z;
      Qt[(ldd + j + 3) * 64 + ldr] = a.w;
    }
  }
  if (tid < 64) { mrow[tid] = -1e30f; lrow[tid] = 0.f; }
  float o[4][4];
#pragma unroll
  for (int i = 0; i < 4; i++)
#pragma unroll
    for (int j = 0; j < 4; j++) o[i][j] = 0.f;

  for (int kb = 0; kb <= qb; kb++) {
    __syncthreads();  // protect Kt/Vs/Ps/red overwrite
    {
      const float* kg = Kg + ((size_t)hk * CT + kb * 64 + ldr) * 64 + ldd;
      const float* vg = Vg + ((size_t)hk * CT + kb * 64 + ldr) * 64 + ldd;
#pragma unroll
      for (int j = 0; j < 16; j += 4) {
        const float4 a = *(const float4*)(kg + j);
        Kt[(ldd + j + 0) * 64 + ldr] = a.x;
        Kt[(ldd + j + 1) * 64 + ldr] = a.y;
        Kt[(ldd + j + 2) * 64 + ldr] = a.z;
        Kt[(ldd + j + 3) * 64 + ldr] = a.w;
        const float4 b = *(const float4*)(vg + j);
        *(float4*)&Vs[ldr * 64 + ldd + j] = b;
      }
    }
    __syncthreads();

    // S = Q K^T
    float s[4][4];
#pragma unroll
    for (int i = 0; i < 4; i++)
#pragma unroll
      for (int j = 0; j < 4; j++) s[i][j] = 0.f;
#pragma unroll
    for (int d = 0; d < 64; d++) {
      const float4 a = *(const float4*)&Qt[d * 64 + r0];
      const float4 b = *(const float4*)&Kt[d * 64 + c0];
      const float ar[4] = {a.x, a.y, a.z, a.w};
      const float br[4] = {b.x, b.y, b.z, b.w};
#pragma unroll
      for (int i = 0; i < 4; i++)
#pragma unroll
        for (int j = 0; j < 4; j++) s[i][j] = fmaf(ar[i], br[j], s[i][j]);
    }

    const int qrow = qb * 64 + r0;
    const int kcol = kb * 64 + c0;
    float rm[4] = {-1e30f, -1e30f, -1e30f, -1e30f};
#pragma unroll
    for (int i = 0; i < 4; i++)
#pragma unroll
      for (int j = 0; j < 4; j++) {
        s[i][j] *= 0.125f;
        if (kcol + j > qrow + i) s[i][j] = -1e30f;
        rm[i] = fmaxf(rm[i], s[i][j]);
      }
#pragma unroll
    for (int i = 0; i < 4; i++) red[(r0 + i) * 16 + tx] = rm[i];
    __syncthreads();
    if (tid < 64) {
      const float mold = mrow[tid];
      float mx = mold;
#pragma unroll
      for (int xx = 0; xx < 16; xx++) mx = fmaxf(mx, red[tid * 16 + xx]);
      const float al = __expf(mold - mx);
      mrow[tid] = mx; arow[tid] = al; lrow[tid] *= al;
    }
    __syncthreads();

    float rs[4] = {0.f, 0.f, 0.f, 0.f};
#pragma unroll
    for (int i = 0; i < 4; i++) {
      const float mi = mrow[r0 + i];
#pragma unroll
      for (int j = 0; j < 4; j++) {
        const float p = __expf(s[i][j] - mi);
        Ps[(c0 + j) * 68 + r0 + i] = p;
        rs[i] += p;
      }
    }
#pragma unroll
    for (int i = 0; i < 4; i++) red[(r0 + i) * 16 + tx] = rs[i];
    // rescale accumulators
#pragma unroll
    for (int i = 0; i < 4; i++) {
      const float al = arow[r0 + i];
#pragma unroll
      for (int j = 0; j < 4; j++) o[i][j] *= al;
    }
    __syncthreads();
    if (tid < 64) {
      float sum = 0.f;
#pragma unroll
      for (int xx = 0; xx < 16; xx++) sum += red[tid * 16 + xx];
      lrow[tid] += sum;
    }
    // O += P V
#pragma unroll
    for (int kk = 0; kk < 64; kk++) {
      const float4 a = *(const float4*)&Ps[kk * 68 + r0];
      const float4 b = *(const float4*)&Vs[kk * 64 + c0];
      const float ar[4] = {a.x, a.y, a.z, a.w};
      const float br[4] = {b.x, b.y, b.z, b.w};
#pragma unroll
      for (int i = 0; i < 4; i++)
#pragma unroll
        for (int j = 0; j < 4; j++) o[i][j] = fmaf(ar[i], br[j], o[i][j]);
    }
  }
  __syncthreads();
#pragma unroll
  for (int i = 0; i < 4; i++) {
    const float inv = 1.f / lrow[r0 + i];
    const float4 v = make_float4(o[i][0] * inv, o[i][1] * inv,
                                 o[i][2] * inv, o[i][3] * inv);
    *(float4*)&Og[(size_t)(qb * 64 + r0 + i) * CD + hh * 64 + c0] = v;
  }
}

// ---------------------------------------------------------------------------
// act = silu(gate) * up  (in place into gate)
// ---------------------------------------------------------------------------
__global__ void silu_mul_kernel(float* __restrict__ gate,
                                const float* __restrict__ up) {
  const size_t i = ((size_t)blockIdx.x * 256 + threadIdx.x) * 4;
  float4 g = *(float4*)&gate[i];
  const float4 u = *(const float4*)&up[i];
  g.x = g.x / (1.f + __expf(-g.x)) * u.x;
  g.y = g.y / (1.f + __expf(-g.y)) * u.y;
  g.z = g.z / (1.f + __expf(-g.z)) * u.z;
  g.w = g.w / (1.f + __expf(-g.w)) * u.w;
  *(float4*)&gate[i] = g;
}

// ---------------------------------------------------------------------------
// Launch pipeline
// ---------------------------------------------------------------------------
extern "C" void kernel_launch(void* const* d_in, const int* in_sizes, int n_in,
                              void* d_out, int out_size) {
  const float* hidden = (const float*)d_in[0];
  const float* ln1 = (const float*)d_in[1];
  const float* ln2 = (const float*)d_in[2];
  const float* q_Us = (const float*)d_in[3];
  const float* q_V  = (const float*)d_in[4];
  const float* k_Us = (const float*)d_in[5];
  const float* k_V  = (const float*)d_in[6];
  const float* v_Us = (const float*)d_in[7];
  const float* v_V  = (const float*)d_in[8];
  const float* o_Us = (const float*)d_in[9];
  const float* o_V  = (const float*)d_in[10];
  const float* g_Us = (const float*)d_in[11];
  const float* g_V  = (const float*)d_in[12];
  const float* u_Us = (const float*)d_in[13];
  const float* u_V  = (const float*)d_in[14];
  const float* d_Us = (const float*)d_in[15];
  const float* d_V  = (const float*)d_in[16];
  float* out = (float*)d_out;

  Scratch* s = nullptr;
  cudaGetSymbolAddress((void**)&s, g_scratch);

  const int faSmem = FA_SMEM_FLOATS * 4;
  cudaFuncSetAttribute(flash_attn, cudaFuncAttributeMaxDynamicSharedMemorySize,
                       faSmem);

  // 1. x = rmsnorm(hidden, ln1)
  rmsnorm_kernel<<<CT, 256>>>(hidden, ln1, s->x);

  // 2. low-rank down-projections (all NT GEMMs)
  sgemm_nt<<<dim3(1024 / 128, CT / 128), 256>>>(s->x, q_V, nullptr, s->Pq, 1024, CD);
  sgemm_nt<<<dim3(256 / 128, CT / 128), 256>>>(s->x, k_V, nullptr, s->Pk, 256, CD);
  sgemm_nt<<<dim3(256 / 128, CT / 128), 256>>>(s->x, v_V, nullptr, s->Pv, 256, CD);

  // 3. Us up-projections + RoPE
  proj_us_rope<<<dim3(CT / 8, CH), dim3(32, 8)>>>(s->Pq, q_Us, s->q, CH, 1);
  proj_us_rope<<<dim3(CT / 8, CHK), dim3(32, 8)>>>(s->Pk, k_Us, s->k, CHK, 1);
  proj_us_rope<<<dim3(CT / 8, CHK), dim3(32, 8)>>>(s->Pv, v_Us, s->v, CHK, 0);

  // 4. attention
  flash_attn<<<dim3(CT / 64, CH), 256, faSmem>>>(s->q, s->k, s->v, s->attn);

  // 5. output projection + residual -> h
  sgemm_nt<<<dim3(512 / 128, CT / 128), 256>>>(s->attn, o_V, nullptr, s->Po, 512, CD);
  sgemm_nt<<<dim3(CD / 128, CT / 128), 256>>>(s->Po, o_Us, hidden, s->h, CD, 512);

  // 6. FFN
  rmsnorm_kernel<<<CT, 256>>>(s->h, ln2, s->x);
  sgemm_nt<<<dim3(512 / 128, CT / 128), 256>>>(s->x, g_V, nullptr, s->Pg, 512, CD);
  sgemm_nt<<<dim3(512 / 128, CT / 128), 256>>>(s->x, u_V, nullptr, s->Pu, 512, CD);
  sgemm_nt<<<dim3(CINTER / 128, CT / 128), 256>>>(s->Pg, g_Us, nullptr, s->gate, CINTER, 512);
  sgemm_nt<<<dim3(CINTER / 128, CT / 128), 256>>>(s->Pu, u_Us, nullptr, s->up, CINTER, 512);
  silu_mul_kernel<<<(CT * CINTER / 4) / 256, 256>>>(s->gate, s->up);
  sgemm_nt<<<dim3(512 / 128, CT / 128), 256>>>(s->gate, d_V, nullptr, s->Pd, 512, CINTER);
  sgemm_nt<<<dim3(CD / 128, CT / 128), 256>>>(s->Pd, d_Us, s->h, out, CD, 512);
}

// round 2
// speedup vs baseline: 2.4798x; 2.4798x over previous
#include <cuda_runtime.h>
#include <math.h>
#include <cstdint>

// ---------------------------------------------------------------------------
// Problem constants (B=1)
// ---------------------------------------------------------------------------
#define CT 2048      // tokens
#define CD 2048      // model dim
#define CH 32        // q heads
#define CHK 8        // kv heads
#define CDH 64       // head dim
#define CINTER 8192  // ffn inner

// ---------------------------------------------------------------------------
// Static device scratch
// ---------------------------------------------------------------------------
struct Scratch {
  float x[CT * CD];
  float Pq[CT * (CH * 32)];
  float Pk[CT * (CHK * 32)];
  float Pv[CT * (CHK * 32)];
  float q[CH * CT * CDH];
  float k[CHK * CT * CDH];
  float v[CHK * CT * CDH];
  float attn[CT * CD];
  float Po[CT * 512];
  float h[CT * CD];
  float Pg[CT * 512];
  float Pu[CT * 512];
  float gate[CT * CINTER];
  float up[CT * CINTER];
  float Pd[CT * 512];
};
__device__ Scratch g_scratch;

// ---------------------------------------------------------------------------
// RMSNorm
// ---------------------------------------------------------------------------
__global__ void rmsnorm_kernel(const float* __restrict__ in,
                               const float* __restrict__ w,
                               float* __restrict__ out) {
  const int t = blockIdx.x;
  const float* row = in + (size_t)t * CD;
  float ss = 0.f;
  for (int i = threadIdx.x; i < CD; i += 256) {
    float v = row[i];
    ss += v * v;
  }
  __shared__ float red[8];
#pragma unroll
  for (int o = 16; o > 0; o >>= 1) ss += __shfl_xor_sync(0xffffffffu, ss, o);
  if ((threadIdx.x & 31) == 0) red[threadIdx.x >> 5] = ss;
  __syncthreads();
  if (threadIdx.x == 0) {
    float v = 0.f;
#pragma unroll
    for (int i = 0; i < 8; i++) v += red[i];
    red[0] = v;
  }
  __syncthreads();
  const float inv = rsqrtf(red[0] * (1.0f / CD) + 1e-5f);
  for (int i = threadIdx.x; i < CD; i += 256)
    out[(size_t)t * CD + i] = row[i] * inv * w[i];
}

// ---------------------------------------------------------------------------
// tf32 tensor-core GEMM (NT): C[M,N] = A[M,K] * B[N,K]^T (+res)
// 128x128 block tile, BK=16, 256 threads (8 warps, 64x32 warp tiles),
// double-buffered cp.async. Requires M%128==0, N%128==0, K%16==0.
// blockIdx.z==1 selects the second (A2,B2,res2,C2) problem (paired launches).
// ---------------------------------------------------------------------------
__device__ __forceinline__ uint32_t f2tf(float x) {
  uint32_t r;
  asm("cvt.rna.tf32.f32 %0, %1;" : "=r"(r) : "f"(x));
  return r;
}
__device__ __forceinline__ void cp16(void* s, const void* g) {
  uint32_t sa = (uint32_t)__cvta_generic_to_shared(s);
  asm volatile("cp.async.cg.shared.global [%0], [%1], 16;" ::"r"(sa), "l"(g));
}
__device__ __forceinline__ void mma_tf32(float* c, const uint32_t* a,
                                         const uint32_t* b) {
  asm volatile(
      "mma.sync.aligned.m16n8k8.row.col.f32.tf32.tf32.f32 "
      "{%0,%1,%2,%3}, {%4,%5,%6,%7}, {%8,%9}, {%0,%1,%2,%3};"
      : "+f"(c[0]), "+f"(c[1]), "+f"(c[2]), "+f"(c[3])
      : "r"(a[0]), "r"(a[1]), "r"(a[2]), "r"(a[3]), "r"(b[0]), "r"(b[1]));
}

__global__ __launch_bounds__(256, 2) void gemm_tf32(
    const float* __restrict__ A1, const float* __restrict__ B1,
    const float* __restrict__ res1, float* __restrict__ C1,
    const float* __restrict__ A2, const float* __restrict__ B2,
    const float* __restrict__ res2, float* __restrict__ C2, int N, int K) {
  const float* A = blockIdx.z ? A2 : A1;
  const float* B = blockIdx.z ? B2 : B1;
  const float* res = blockIdx.z ? res2 : res1;
  float* C = blockIdx.z ? C2 : C1;

  __shared__ float As[2][128][20];
  __shared__ float Bs[2][128][20];

  const int tid = threadIdx.x;
  const int lane = tid & 31;
  const int warp = tid >> 5;
  const int wm = (warp & 1) * 64;
  const int wn = (warp >> 1) * 32;
  const int bm = blockIdx.y * 128;
  const int bn = blockIdx.x * 128;
  const int gi = lane >> 2;   // group id (0..7)
  const int ti = lane & 3;    // thread-in-group

  // global->smem mapping: row = tid>>1, two float4 at kseg, kseg+4
  const int grow = tid >> 1;
  const int kseg = (tid & 1) * 8;

  float acc[4][4][4];
#pragma unroll
  for (int i = 0; i < 4; i++)
#pragma unroll
    for (int j = 0; j < 4; j++)
#pragma unroll
      for (int l = 0; l < 4; l++) acc[i][j][l] = 0.f;

  const int nt = K >> 4;

  // prefetch tile 0
  {
    const float* ga = &A[(size_t)(bm + grow) * K + kseg];
    cp16(&As[0][grow][kseg], ga);
    cp16(&As[0][grow][kseg + 4], ga + 4);
    const float* gb = &B[(size_t)(bn + grow) * K + kseg];
    cp16(&Bs[0][grow][kseg], gb);
    cp16(&Bs[0][grow][kseg + 4], gb + 4);
    asm volatile("cp.async.commit_group;" ::: "memory");
  }

  for (int t = 0; t < nt; t++) {
    const int buf = t & 1;
    if (t + 1 < nt) {
      const int k0 = (t + 1) << 4;
      const float* ga = &A[(size_t)(bm + grow) * K + k0 + kseg];
      cp16(&As[buf ^ 1][grow][kseg], ga);
      cp16(&As[buf ^ 1][grow][kseg + 4], ga + 4);
      const float* gb = &B[(size_t)(bn + grow) * K + k0 + kseg];
      cp16(&Bs[buf ^ 1][grow][kseg], gb);
      cp16(&Bs[buf ^ 1][grow][kseg + 4], gb + 4);
      asm volatile("cp.async.commit_group;" ::: "memory");
      asm volatile("cp.async.wait_group 1;" ::: "memory");
    } else {
      asm volatile("cp.async.wait_group 0;" ::: "memory");
    }
    __syncthreads();

#pragma unroll
    for (int kk = 0; kk < 2; kk++) {
      const int kb = kk * 8 + ti;
      uint32_t a[4][4], b[4][2];
#pragma unroll
      for (int fm = 0; fm < 4; fm++) {
        const float* p0 = &As[buf][wm + fm * 16 + gi][kb];
        const float* p1 = &As[buf][wm + fm * 16 + 8 + gi][kb];
        a[fm][0] = f2tf(p0[0]);
        a[fm][1] = f2tf(p1[0]);
        a[fm][2] = f2tf(p0[4]);
        a[fm][3] = f2tf(p1[4]);
      }
#pragma unroll
      for (int fn = 0; fn < 4; fn++) {
        const float* p = &Bs[buf][wn + fn * 8 + gi][kb];
        b[fn][0] = f2tf(p[0]);
        b[fn][1] = f2tf(p[4]);
      }
#pragma unroll
      for (int fm = 0; fm < 4; fm++)
#pragma unroll
        for (int fn = 0; fn < 4; fn++) mma_tf32(acc[fm][fn], a[fm], b[fn]);
    }
    __syncthreads();
  }

  // epilogue
#pragma unroll
  for (int fm = 0; fm < 4; fm++) {
#pragma unroll
    for (int fn = 0; fn < 4; fn++) {
      const int r = bm + wm + fm * 16 + gi;
      const int c = bn + wn + fn * 8 + ti * 2;
      float2 v0 = make_float2(acc[fm][fn][0], acc[fm][fn][1]);
      float2 v1 = make_float2(acc[fm][fn][2], acc[fm][fn][3]);
      if (res) {
        const float2 r0 = *(const float2*)&res[(size_t)r * N + c];
        const float2 r1 = *(const float2*)&res[(size_t)(r + 8) * N + c];
        v0.x += r0.x; v0.y += r0.y;
        v1.x += r1.x; v1.y += r1.y;
      }
      *(float2*)&C[(size_t)r * N + c] = v0;
      *(float2*)&C[(size_t)(r + 8) * N + c] = v1;
    }
  }
}

// ---------------------------------------------------------------------------
// Per-head Us projection (rank 32 -> head dim 64) with optional fused RoPE.
// ---------------------------------------------------------------------------
__global__ void proj_us_rope(const float* __restrict__ P,
                             const float* __restrict__ Us,
                             float* __restrict__ out, int nheads, int doRope) {
  const int hh = blockIdx.y;
  const int tt = threadIdx.y;
  const int t = blockIdx.x * 8 + tt;
  const int dh = threadIdx.x;  // 0..31
  __shared__ float sUs[64][32];
  __shared__ float sP[8][32];
  const int tid = tt * 32 + dh;
  const float* UsH = Us + (size_t)hh * 64 * 32;
#pragma unroll
  for (int i = tid; i < 64 * 32; i += 256) sUs[i >> 5][i & 31] = UsH[i];
  sP[tt][dh] = P[(size_t)t * (nheads * 32) + hh * 32 + dh];
  __syncthreads();
  float x1 = 0.f, x2 = 0.f;
#pragma unroll
  for (int r = 0; r < 32; r++) {
    const float p = sP[tt][r];
    x1 = fmaf(p, sUs[dh][r], x1);
    x2 = fmaf(p, sUs[dh + 32][r], x2);
  }
  float o1 = x1, o2 = x2;
  if (doRope) {
    const float invf = exp2f(-0.41524101186092028f * (float)dh);
    const float ang = (float)t * invf;
    float sn, cs;
    sincosf(ang, &sn, &cs);
    o1 = x1 * cs - x2 * sn;
    o2 = x2 * cs + x1 * sn;
  }
  const size_t base = ((size_t)hh * CT + t) * CDH;
  out[base + dh] = o1;
  out[base + dh + 32] = o2;
}

// ---------------------------------------------------------------------------
// Causal flash attention, fp32. 64x64 tiles, Dh=64, GQA rep 4. (unchanged)
// ---------------------------------------------------------------------------
#define FA_SMEM_FLOATS (4096 * 3 + 64 * 68 + 64 * 3 + 64 * 16)
__global__ __launch_bounds__(256) void flash_attn(
    const float* __restrict__ Q, const float* __restrict__ Kg,
    const float* __restrict__ Vg, float* __restrict__ Og) {
  extern __shared__ float sm[];
  float* Qt = sm;
  float* Kt = sm + 4096;
  float* Vs = sm + 8192;
  float* Ps = sm + 12288;
  float* mrow = Ps + 64 * 68;
  float* lrow = mrow + 64;
  float* arow = lrow + 64;
  float* red = arow + 64;

  const int qb = blockIdx.x, hh = blockIdx.y, hk = hh >> 2;
  const int tid = threadIdx.x;
  const int tx = tid & 15, ty = tid >> 4;
  const int r0 = ty * 4, c0 = tx * 4;
  const int ldr = tid >> 2;
  const int ldd = (tid & 3) * 16;

  {
    const float* qg = Q + ((size_t)hh * CT + qb * 64 + ldr) * 64 + ldd;
#pragma unroll
    for (int j = 0; j < 16; j += 4) {
      const float4 a = *(const float4*)(qg + j);
      Qt[(ldd + j + 0) * 64 + ldr] = a.x;
      Qt[(ldd + j + 1) * 64 + ldr] = a.y;
      Qt[(ldd + j + 2) * 64 + ldr] = a.z;
      Qt[(ldd + j + 3) * 64 + ldr] = a.w;
    }
  }
  if (tid < 64) { mrow[tid] = -1e30f; lrow[tid] = 0.f; }
  float o[4][4];
#pragma unroll
  for (int i = 0; i < 4; i++)
#pragma unroll
    for (int j = 0; j < 4; j++) o[i][j] = 0.f;

  for (int kb = 0; kb <= qb; kb++) {
    __syncthreads();
    {
      const float* kg = Kg + ((size_t)hk * CT + kb * 64 + ldr) * 64 + ldd;
      const float* vg = Vg + ((size_t)hk * CT + kb * 64 + ldr) * 64 + ldd;
#pragma unroll
      for (int j = 0; j < 16; j += 4) {
        const float4 a = *(const float4*)(kg + j);
        Kt[(ldd + j + 0) * 64 + ldr] = a.x;
        Kt[(ldd + j + 1) * 64 + ldr] = a.y;
        Kt[(ldd + j + 2) * 64 + ldr] = a.z;
        Kt[(ldd + j + 3) * 64 + ldr] = a.w;
        const float4 b = *(const float4*)(vg + j);
        *(float4*)&Vs[ldr * 64 + ldd + j] = b;
      }
    }
    __syncthreads();

    float s[4][4];
#pragma unroll
    for (int i = 0; i < 4; i++)
#pragma unroll
      for (int j = 0; j < 4; j++) s[i][j] = 0.f;
#pragma unroll
    for (int d = 0; d < 64; d++) {
      const float4 a = *(const float4*)&Qt[d * 64 + r0];
      const float4 b = *(const float4*)&Kt[d * 64 + c0];
      const float ar[4] = {a.x, a.y, a.z, a.w};
      const float br[4] = {b.x, b.y, b.z, b.w};
#pragma unroll
      for (int i = 0; i < 4; i++)
#pragma unroll
        for (int j = 0; j < 4; j++) s[i][j] = fmaf(ar[i], br[j], s[i][j]);
    }

    const int qrow = qb * 64 + r0;
    const int kcol = kb * 64 + c0;
    float rm[4] = {-1e30f, -1e30f, -1e30f, -1e30f};
#pragma unroll
    for (int i = 0; i < 4; i++)
#pragma unroll
      for (int j = 0; j < 4; j++) {
        s[i][j] *= 0.125f;
        if (kcol + j > qrow + i) s[i][j] = -1e30f;
        rm[i] = fmaxf(rm[i], s[i][j]);
      }
#pragma unroll
    for (int i = 0; i < 4; i++) red[(r0 + i) * 16 + tx] = rm[i];
    __syncthreads();
    if (tid < 64) {
      const float mold = mrow[tid];
      float mx = mold;
#pragma unroll
      for (int xx = 0; xx < 16; xx++) mx = fmaxf(mx, red[tid * 16 + xx]);
      const float al = __expf(mold - mx);
      mrow[tid] = mx; arow[tid] = al; lrow[tid] *= al;
    }
    __syncthreads();

    float rs[4] = {0.f, 0.f, 0.f, 0.f};
#pragma unroll
    for (int i = 0; i < 4; i++) {
      const float mi = mrow[r0 + i];
#pragma unroll
      for (int j = 0; j < 4; j++) {
        const float p = __expf(s[i][j] - mi);
        Ps[(c0 + j) * 68 + r0 + i] = p;
        rs[i] += p;
      }
    }
#pragma unroll
    for (int i = 0; i < 4; i++) red[(r0 + i) * 16 + tx] = rs[i];
#pragma unroll
    for (int i = 0; i < 4; i++) {
      const float al = arow[r0 + i];
#pragma unroll
      for (int j = 0; j < 4; j++) o[i][j] *= al;
    }
    __syncthreads();
    if (tid < 64) {
      float sum = 0.f;
#pragma unroll
      for (int xx = 0; xx < 16; xx++) sum += red[tid * 16 + xx];
      lrow[tid] += sum;
    }
#pragma unroll
    for (int kk = 0; kk < 64; kk++) {
      const float4 a = *(const float4*)&Ps[kk * 68 + r0];
      const float4 b = *(const float4*)&Vs[kk * 64 + c0];
      const float ar[4] = {a.x, a.y, a.z, a.w};
      const float br[4] = {b.x, b.y, b.z, b.w};
#pragma unroll
      for (int i = 0; i < 4; i++)
#pragma unroll
        for (int j = 0; j < 4; j++) o[i][j] = fmaf(ar[i], br[j], o[i][j]);
    }
  }
  __syncthreads();
#pragma unroll
  for (int i = 0; i < 4; i++) {
    const float inv = 1.f / lrow[r0 + i];
    const float4 v = make_float4(o[i][0] * inv, o[i][1] * inv,
                                 o[i][2] * inv, o[i][3] * inv);
    *(float4*)&Og[(size_t)(qb * 64 + r0 + i) * CD + hh * 64 + c0] = v;
  }
}

// ---------------------------------------------------------------------------
// act = silu(gate) * up  (in place into gate)
// ---------------------------------------------------------------------------
__global__ void silu_mul_kernel(float* __restrict__ gate,
                                const float* __restrict__ up) {
  const size_t i = ((size_t)blockIdx.x * 256 + threadIdx.x) * 4;
  float4 g = *(float4*)&gate[i];
  const float4 u = *(const float4*)&up[i];
  g.x = g.x / (1.f + __expf(-g.x)) * u.x;
  g.y = g.y / (1.f + __expf(-g.y)) * u.y;
  g.z = g.z / (1.f + __expf(-g.z)) * u.z;
  g.w = g.w / (1.f + __expf(-g.w)) * u.w;
  *(float4*)&gate[i] = g;
}

// ---------------------------------------------------------------------------
// Launch pipeline
// ---------------------------------------------------------------------------
extern "C" void kernel_launch(void* const* d_in, const int* in_sizes, int n_in,
                              void* d_out, int out_size) {
  const float* hidden = (const float*)d_in[0];
  const float* ln1 = (const float*)d_in[1];
  const float* ln2 = (const float*)d_in[2];
  const float* q_Us = (const float*)d_in[3];
  const float* q_V  = (const float*)d_in[4];
  const float* k_Us = (const float*)d_in[5];
  const float* k_V  = (const float*)d_in[6];
  const float* v_Us = (const float*)d_in[7];
  const float* v_V  = (const float*)d_in[8];
  const float* o_Us = (const float*)d_in[9];
  const float* o_V  = (const float*)d_in[10];
  const float* g_Us = (const float*)d_in[11];
  const float* g_V  = (const float*)d_in[12];
  const float* u_Us = (const float*)d_in[13];
  const float* u_V  = (const float*)d_in[14];
  const float* d_Us = (const float*)d_in[15];
  const float* d_V  = (const float*)d_in[16];
  float* out = (float*)d_out;

  Scratch* s = nullptr;
  cudaGetSymbolAddress((void**)&s, g_scratch);

  const int faSmem = FA_SMEM_FLOATS * 4;
  cudaFuncSetAttribute(flash_attn, cudaFuncAttributeMaxDynamicSharedMemorySize,
                       faSmem);

  // 1. x = rmsnorm(hidden, ln1)
  rmsnorm_kernel<<<CT, 256>>>(hidden, ln1, s->x);

  // 2. low-rank down-projections
  gemm_tf32<<<dim3(8, 16, 1), 256>>>(s->x, q_V, nullptr, s->Pq,
                                     nullptr, nullptr, nullptr, nullptr,
                                     1024, CD);
  gemm_tf32<<<dim3(2, 16, 2), 256>>>(s->x, k_V, nullptr, s->Pk,
                                     s->x, v_V, nullptr, s->Pv, 256, CD);

  // 3. Us up-projections + RoPE
  proj_us_rope<<<dim3(CT / 8, CH), dim3(32, 8)>>>(s->Pq, q_Us, s->q, CH, 1);
  proj_us_rope<<<dim3(CT / 8, CHK), dim3(32, 8)>>>(s->Pk, k_Us, s->k, CHK, 1);
  proj_us_rope<<<dim3(CT / 8, CHK), dim3(32, 8)>>>(s->Pv, v_Us, s->v, CHK, 0);

  // 4. attention
  flash_attn<<<dim3(CT / 64, CH), 256, faSmem>>>(s->q, s->k, s->v, s->attn);

  // 5. output projection + residual -> h
  gemm_tf32<<<dim3(4, 16, 1), 256>>>(s->attn, o_V, nullptr, s->Po,
                                     nullptr, nullptr, nullptr, nullptr,
                                     512, CD);
  gemm_tf32<<<dim3(16, 16, 1), 256>>>(s->Po, o_Us, hidden, s->h,
                                      nullptr, nullptr, nullptr, nullptr,
                                      CD, 512);

  // 6. FFN
  rmsnorm_kernel<<<CT, 256>>>(s->h, ln2, s->x);
  gemm_tf32<<<dim3(4, 16, 2), 256>>>(s->x, g_V, nullptr, s->Pg,
                                     s->x, u_V, nullptr, s->Pu, 512, CD);
  gemm_tf32<<<dim3(64, 16, 2), 256>>>(s->Pg, g_Us, nullptr, s->gate,
                                      s->Pu, u_Us, nullptr, s->up,
                                      CINTER, 512);
  silu_mul_kernel<<<(CT * CINTER / 4) / 256, 256>>>(s->gate, s->up);
  gemm_tf32<<<dim3(4, 16, 1), 256>>>(s->gate, d_V, nullptr, s->Pd,
                                     nullptr, nullptr, nullptr, nullptr,
                                     512, CINTER);
  gemm_tf32<<<dim3(16, 16, 1), 256>>>(s->Pd, d_Us, s->h, out,
                                      nullptr, nullptr, nullptr, nullptr,
                                      CD, 512);
}

// round 3
// speedup vs baseline: 3.3663x; 1.3575x over previous
#include <cuda_runtime.h>
#include <math.h>
#include <cstdint>

// ---------------------------------------------------------------------------
// Problem constants (B=1)
// ---------------------------------------------------------------------------
#define CT 2048      // tokens
#define CD 2048      // model dim
#define CH 32        // q heads
#define CHK 8        // kv heads
#define CDH 64       // head dim
#define CINTER 8192  // ffn inner

// ---------------------------------------------------------------------------
// Static device scratch
// ---------------------------------------------------------------------------
struct Scratch {
  float x[CT * CD];
  float Pq[CT * (CH * 32)];
  float Pk[CT * (CHK * 32)];
  float Pv[CT * (CHK * 32)];
  float q[CH * CT * CDH];
  float k[CHK * CT * CDH];
  float v[CHK * CT * CDH];
  float attn[CT * CD];
  float Po[CT * 512];
  float h[CT * CD];
  float Pg[CT * 512];
  float Pu[CT * 512];
  float gate[CT * CINTER];
  float up[CT * CINTER];
  float Pd[CT * 512];
};
__device__ Scratch g_scratch;

// ---------------------------------------------------------------------------
// mma helpers
// ---------------------------------------------------------------------------
__device__ __forceinline__ uint32_t f2tf(float x) {
  uint32_t r;
  asm("cvt.rna.tf32.f32 %0, %1;" : "=r"(r) : "f"(x));
  return r;
}
__device__ __forceinline__ void cp16(void* s, const void* g) {
  uint32_t sa = (uint32_t)__cvta_generic_to_shared(s);
  asm volatile("cp.async.cg.shared.global [%0], [%1], 16;" ::"r"(sa), "l"(g));
}
__device__ __forceinline__ void mma_tf32(float* c, const uint32_t* a,
                                         const uint32_t* b) {
  asm volatile(
      "mma.sync.aligned.m16n8k8.row.col.f32.tf32.tf32.f32 "
      "{%0,%1,%2,%3}, {%4,%5,%6,%7}, {%8,%9}, {%0,%1,%2,%3};"
      : "+f"(c[0]), "+f"(c[1]), "+f"(c[2]), "+f"(c[3])
      : "r"(a[0]), "r"(a[1]), "r"(a[2]), "r"(a[3]), "r"(b[0]), "r"(b[1]));
}

// ---------------------------------------------------------------------------
// RMSNorm
// ---------------------------------------------------------------------------
__global__ void rmsnorm_kernel(const float* __restrict__ in,
                               const float* __restrict__ w,
                               float* __restrict__ out) {
  const int t = blockIdx.x;
  const float* row = in + (size_t)t * CD;
  float ss = 0.f;
  for (int i = threadIdx.x; i < CD; i += 256) {
    float v = row[i];
    ss += v * v;
  }
  __shared__ float red[8];
#pragma unroll
  for (int o = 16; o > 0; o >>= 1) ss += __shfl_xor_sync(0xffffffffu, ss, o);
  if ((threadIdx.x & 31) == 0) red[threadIdx.x >> 5] = ss;
  __syncthreads();
  if (threadIdx.x == 0) {
    float v = 0.f;
#pragma unroll
    for (int i = 0; i < 8; i++) v += red[i];
    red[0] = v;
  }
  __syncthreads();
  const float inv = rsqrtf(red[0] * (1.0f / CD) + 1e-5f);
  for (int i = threadIdx.x; i < CD; i += 256)
    out[(size_t)t * CD + i] = row[i] * inv * w[i];
}

// ---------------------------------------------------------------------------
// tf32 tensor-core GEMM (NT): C = A * B^T (+res). 128x128x16 tiles.
// ---------------------------------------------------------------------------
__global__ __launch_bounds__(256, 2) void gemm_tf32(
    const float* __restrict__ A1, const float* __restrict__ B1,
    const float* __restrict__ res1, float* __restrict__ C1,
    const float* __restrict__ A2, const float* __restrict__ B2,
    const float* __restrict__ res2, float* __restrict__ C2, int N, int K) {
  const float* A = blockIdx.z ? A2 : A1;
  const float* B = blockIdx.z ? B2 : B1;
  const float* res = blockIdx.z ? res2 : res1;
  float* C = blockIdx.z ? C2 : C1;

  __shared__ float As[2][128][20];
  __shared__ float Bs[2][128][20];

  const int tid = threadIdx.x;
  const int lane = tid & 31;
  const int warp = tid >> 5;
  const int wm = (warp & 1) * 64;
  const int wn = (warp >> 1) * 32;
  const int bm = blockIdx.y * 128;
  const int bn = blockIdx.x * 128;
  const int gi = lane >> 2;
  const int ti = lane & 3;
  const int grow = tid >> 1;
  const int kseg = (tid & 1) * 8;

  float acc[4][4][4];
#pragma unroll
  for (int i = 0; i < 4; i++)
#pragma unroll
    for (int j = 0; j < 4; j++)
#pragma unroll
      for (int l = 0; l < 4; l++) acc[i][j][l] = 0.f;

  const int nt = K >> 4;
  {
    const float* ga = &A[(size_t)(bm + grow) * K + kseg];
    cp16(&As[0][grow][kseg], ga);
    cp16(&As[0][grow][kseg + 4], ga + 4);
    const float* gb = &B[(size_t)(bn + grow) * K + kseg];
    cp16(&Bs[0][grow][kseg], gb);
    cp16(&Bs[0][grow][kseg + 4], gb + 4);
    asm volatile("cp.async.commit_group;" ::: "memory");
  }

  for (int t = 0; t < nt; t++) {
    const int buf = t & 1;
    if (t + 1 < nt) {
      const int k0 = (t + 1) << 4;
      const float* ga = &A[(size_t)(bm + grow) * K + k0 + kseg];
      cp16(&As[buf ^ 1][grow][kseg], ga);
      cp16(&As[buf ^ 1][grow][kseg + 4], ga + 4);
      const float* gb = &B[(size_t)(bn + grow) * K + k0 + kseg];
      cp16(&Bs[buf ^ 1][grow][kseg], gb);
      cp16(&Bs[buf ^ 1][grow][kseg + 4], gb + 4);
      asm volatile("cp.async.commit_group;" ::: "memory");
      asm volatile("cp.async.wait_group 1;" ::: "memory");
    } else {
      asm volatile("cp.async.wait_group 0;" ::: "memory");
    }
    __syncthreads();

#pragma unroll
    for (int kk = 0; kk < 2; kk++) {
      const int kb = kk * 8 + ti;
      uint32_t a[4][4], b[4][2];
#pragma unroll
      for (int fm = 0; fm < 4; fm++) {
        const float* p0 = &As[buf][wm + fm * 16 + gi][kb];
        const float* p1 = &As[buf][wm + fm * 16 + 8 + gi][kb];
        a[fm][0] = f2tf(p0[0]);
        a[fm][1] = f2tf(p1[0]);
        a[fm][2] = f2tf(p0[4]);
        a[fm][3] = f2tf(p1[4]);
      }
#pragma unroll
      for (int fn = 0; fn < 4; fn++) {
        const float* p = &Bs[buf][wn + fn * 8 + gi][kb];
        b[fn][0] = f2tf(p[0]);
        b[fn][1] = f2tf(p[4]);
      }
#pragma unroll
      for (int fm = 0; fm < 4; fm++)
#pragma unroll
        for (int fn = 0; fn < 4; fn++) mma_tf32(acc[fm][fn], a[fm], b[fn]);
    }
    __syncthreads();
  }

#pragma unroll
  for (int fm = 0; fm < 4; fm++) {
#pragma unroll
    for (int fn = 0; fn < 4; fn++) {
      const int r = bm + wm + fm * 16 + gi;
      const int c = bn + wn + fn * 8 + ti * 2;
      float2 v0 = make_float2(acc[fm][fn][0], acc[fm][fn][1]);
      float2 v1 = make_float2(acc[fm][fn][2], acc[fm][fn][3]);
      if (res) {
        const float2 r0 = *(const float2*)&res[(size_t)r * N + c];
        const float2 r1 = *(const float2*)&res[(size_t)(r + 8) * N + c];
        v0.x += r0.x; v0.y += r0.y;
        v1.x += r1.x; v1.y += r1.y;
      }
      *(float2*)&C[(size_t)r * N + c] = v0;
      *(float2*)&C[(size_t)(r + 8) * N + c] = v1;
    }
  }
}

// ---------------------------------------------------------------------------
// Per-head Us projection (rank 32 -> 64) + optional RoPE.
// grid (T/32, nheads), block (32,8); each thread-group row handles 4 tokens.
// sUs padded to 33: bank = dh + r (conflict-free).
// ---------------------------------------------------------------------------
__global__ void proj_us_rope(const float* __restrict__ P,
                             const float* __restrict__ Us,
                             float* __restrict__ out, int nheads, int doRope) {
  const int hh = blockIdx.y;
  const int tg = threadIdx.y;        // 0..7
  const int dh = threadIdx.x;        // 0..31
  const int t0 = blockIdx.x * 32 + tg * 4;
  __shared__ float sUs[64][33];
  __shared__ float sP[32][33];
  const int tid = tg * 32 + dh;
  const float* UsH = Us + (size_t)hh * 64 * 32;
#pragma unroll
  for (int i = tid; i < 64 * 32; i += 256) sUs[i >> 5][i & 31] = UsH[i];
#pragma unroll
  for (int j = 0; j < 4; j++)
    sP[tg * 4 + j][dh] = P[(size_t)(t0 + j) * (nheads * 32) + hh * 32 + dh];
  __syncthreads();
  float x1[4] = {0.f, 0.f, 0.f, 0.f}, x2[4] = {0.f, 0.f, 0.f, 0.f};
#pragma unroll
  for (int r = 0; r < 32; r++) {
    const float u1 = sUs[dh][r];
    const float u2 = sUs[dh + 32][r];
#pragma unroll
    for (int j = 0; j < 4; j++) {
      const float p = sP[tg * 4 + j][r];
      x1[j] = fmaf(p, u1, x1[j]);
      x2[j] = fmaf(p, u2, x2[j]);
    }
  }
  float sn = 0.f, cs = 1.f;
  const float invf = exp2f(-0.41524101186092028f * (float)dh);
#pragma unroll
  for (int j = 0; j < 4; j++) {
    float o1 = x1[j], o2 = x2[j];
    if (doRope) {
      sincosf((float)(t0 + j) * invf, &sn, &cs);
      o1 = x1[j] * cs - x2[j] * sn;
      o2 = x2[j] * cs + x1[j] * sn;
    }
    const size_t base = ((size_t)hh * CT + t0 + j) * CDH;
    out[base + dh] = o1;
    out[base + dh + 32] = o2;
  }
}

// ---------------------------------------------------------------------------
// tf32 causal flash attention. 64x64 tiles, Dh=64, GQA rep 4.
// 8 warps: warp_m = warp>>1 (16 rows), warp_n = warp&1 (32 cols).
// ---------------------------------------------------------------------------
#define FTS 68
#define FA_SMEM_FLOATS (4 * 64 * FTS + 64 * 3 + 64 * 4)
__global__ __launch_bounds__(256) void flash_attn_tf32(
    const float* __restrict__ Q, const float* __restrict__ Kg,
    const float* __restrict__ Vg, float* __restrict__ Og) {
  extern __shared__ float sm[];
  float* Qs = sm;                  // [64][FTS] row-major [q][dh]
  float* Ks = Qs + 64 * FTS;       // [64][FTS] row-major [k][dh]
  float* Vt = Ks + 64 * FTS;       // [64][FTS] transposed [dh][k]
  float* Ps = Vt + 64 * FTS;       // [64][FTS] [q][k]
  float* mrow = Ps + 64 * FTS;
  float* lrow = mrow + 64;
  float* arow = lrow + 64;
  float* redm = arow + 64;         // [64][2]
  float* redl = redm + 128;        // [64][2]

  const int qb = blockIdx.x, hh = blockIdx.y, hk = hh >> 2;
  const int tid = threadIdx.x;
  const int lane = tid & 31, warp = tid >> 5;
  const int gi = lane >> 2, ti = lane & 3;
  const int wm = (warp >> 1) * 16;
  const int wn = (warp & 1) * 32;
  const int ldr = tid >> 2, ldd = (tid & 3) * 16;

  {
    const float* qg = Q + ((size_t)hh * CT + qb * 64 + ldr) * 64 + ldd;
#pragma unroll
    for (int j = 0; j < 16; j += 4)
      *(float4*)&Qs[ldr * FTS + ldd + j] = *(const float4*)(qg + j);
  }
  if (tid < 64) { mrow[tid] = -1e30f; lrow[tid] = 0.f; }

  float oacc[4][4];
#pragma unroll
  for (int i = 0; i < 4; i++)
#pragma unroll
    for (int j = 0; j < 4; j++) oacc[i][j] = 0.f;

  for (int kb = 0; kb <= qb; kb++) {
    __syncthreads();
    {
      const float* kg = Kg + ((size_t)hk * CT + kb * 64 + ldr) * 64 + ldd;
      const float* vg = Vg + ((size_t)hk * CT + kb * 64 + ldr) * 64 + ldd;
#pragma unroll
      for (int j = 0; j < 16; j += 4) {
        *(float4*)&Ks[ldr * FTS + ldd + j] = *(const float4*)(kg + j);
        const float4 v4 = *(const float4*)(vg + j);
        Vt[(ldd + j + 0) * FTS + ldr] = v4.x;
        Vt[(ldd + j + 1) * FTS + ldr] = v4.y;
        Vt[(ldd + j + 2) * FTS + ldr] = v4.z;
        Vt[(ldd + j + 3) * FTS + ldr] = v4.w;
      }
    }
    __syncthreads();

    // S = Q K^T
    float sacc[4][4];
#pragma unroll
    for (int i = 0; i < 4; i++)
#pragma unroll
      for (int j = 0; j < 4; j++) sacc[i][j] = 0.f;
#pragma unroll
    for (int ks = 0; ks < 8; ks++) {
      const int kc = ks * 8 + ti;
      uint32_t a[4], b[4][2];
      a[0] = f2tf(Qs[(wm + gi) * FTS + kc]);
      a[1] = f2tf(Qs[(wm + gi + 8) * FTS + kc]);
      a[2] = f2tf(Qs[(wm + gi) * FTS + kc + 4]);
      a[3] = f2tf(Qs[(wm + gi + 8) * FTS + kc + 4]);
#pragma unroll
      for (int fn = 0; fn < 4; fn++) {
        b[fn][0] = f2tf(Ks[(wn + fn * 8 + gi) * FTS + kc]);
        b[fn][1] = f2tf(Ks[(wn + fn * 8 + gi) * FTS + kc + 4]);
      }
#pragma unroll
      for (int fn = 0; fn < 4; fn++) mma_tf32(sacc[fn], a, b[fn]);
    }

    // scale + causal mask + partial row max
    const bool diag = (kb == qb);
    float rmax0 = -1e30f, rmax1 = -1e30f;
#pragma unroll
    for (int fn = 0; fn < 4; fn++) {
      const int c = wn + fn * 8 + 2 * ti;
#pragma unroll
      for (int l = 0; l < 4; l++) {
        float v = sacc[fn][l] * 0.125f;
        const int row = wm + gi + ((l >= 2) ? 8 : 0);
        const int col = c + (l & 1);
        if (diag && col > row) v = -1e30f;
        sacc[fn][l] = v;
        if (l >= 2) rmax1 = fmaxf(rmax1, v);
        else rmax0 = fmaxf(rmax0, v);
      }
    }
    rmax0 = fmaxf(rmax0, __shfl_xor_sync(0xffffffffu, rmax0, 1));
    rmax0 = fmaxf(rmax0, __shfl_xor_sync(0xffffffffu, rmax0, 2));
    rmax1 = fmaxf(rmax1, __shfl_xor_sync(0xffffffffu, rmax1, 1));
    rmax1 = fmaxf(rmax1, __shfl_xor_sync(0xffffffffu, rmax1, 2));
    if (ti == 0) {
      redm[(wm + gi) * 2 + (warp & 1)] = rmax0;
      redm[(wm + gi + 8) * 2 + (warp & 1)] = rmax1;
    }
    __syncthreads();
    if (tid < 64) {
      const float mold = mrow[tid];
      const float mnew = fmaxf(mold, fmaxf(redm[tid * 2], redm[tid * 2 + 1]));
      const float al = __expf(mold - mnew);
      mrow[tid] = mnew; arow[tid] = al; lrow[tid] *= al;
    }
    __syncthreads();

    const float m0 = mrow[wm + gi], m1 = mrow[wm + gi + 8];
    const float a0 = arow[wm + gi], a1 = arow[wm + gi + 8];
    float rs0 = 0.f, rs1 = 0.f;
#pragma unroll
    for (int fn = 0; fn < 4; fn++) {
      const int c = wn + fn * 8 + 2 * ti;
      const float p00 = __expf(sacc[fn][0] - m0);
      const float p01 = __expf(sacc[fn][1] - m0);
      const float p10 = __expf(sacc[fn][2] - m1);
      const float p11 = __expf(sacc[fn][3] - m1);
      rs0 += p00 + p01; rs1 += p10 + p11;
      *(float2*)&Ps[(wm + gi) * FTS + c] = make_float2(p00, p01);
      *(float2*)&Ps[(wm + gi + 8) * FTS + c] = make_float2(p10, p11);
    }
    rs0 += __shfl_xor_sync(0xffffffffu, rs0, 1);
    rs0 += __shfl_xor_sync(0xffffffffu, rs0, 2);
    rs1 += __shfl_xor_sync(0xffffffffu, rs1, 1);
    rs1 += __shfl_xor_sync(0xffffffffu, rs1, 2);
    if (ti == 0) {
      redl[(wm + gi) * 2 + (warp & 1)] = rs0;
      redl[(wm + gi + 8) * 2 + (warp & 1)] = rs1;
    }
    // rescale accumulators
#pragma unroll
    for (int fn = 0; fn < 4; fn++) {
      oacc[fn][0] *= a0; oacc[fn][1] *= a0;
      oacc[fn][2] *= a1; oacc[fn][3] *= a1;
    }
    __syncthreads();
    if (tid < 64) lrow[tid] += redl[tid * 2] + redl[tid * 2 + 1];

    // O += P V
#pragma unroll
    for (int ks = 0; ks < 8; ks++) {
      const int kc = ks * 8 + ti;
      uint32_t a[4], b[4][2];
      a[0] = f2tf(Ps[(wm + gi) * FTS + kc]);
      a[1] = f2tf(Ps[(wm + gi + 8) * FTS + kc]);
      a[2] = f2tf(Ps[(wm + gi) * FTS + kc + 4]);
      a[3] = f2tf(Ps[(wm + gi + 8) * FTS + kc + 4]);
#pragma unroll
      for (int fn = 0; fn < 4; fn++) {
        b[fn][0] = f2tf(Vt[(wn + fn * 8 + gi) * FTS + kc]);
        b[fn][1] = f2tf(Vt[(wn + fn * 8 + gi) * FTS + kc + 4]);
      }
#pragma unroll
      for (int fn = 0; fn < 4; fn++) mma_tf32(oacc[fn], a, b[fn]);
    }
  }
  __syncthreads();

  const float inv0 = 1.f / lrow[wm + gi];
  const float inv1 = 1.f / lrow[wm + gi + 8];
#pragma unroll
  for (int fn = 0; fn < 4; fn++) {
    const int col = hh * 64 + wn + fn * 8 + 2 * ti;
    *(float2*)&Og[(size_t)(qb * 64 + wm + gi) * CD + col] =
        make_float2(oacc[fn][0] * inv0, oacc[fn][1] * inv0);
    *(float2*)&Og[(size_t)(qb * 64 + wm + gi + 8) * CD + col] =
        make_float2(oacc[fn][2] * inv1, oacc[fn][3] * inv1);
  }
}

// ---------------------------------------------------------------------------
// act = silu(gate) * up
// ---------------------------------------------------------------------------
__global__ void silu_mul_kernel(float* __restrict__ gate,
                                const float* __restrict__ up) {
  const size_t i = ((size_t)blockIdx.x * 256 + threadIdx.x) * 4;
  float4 g = *(float4*)&gate[i];
  const float4 u = *(const float4*)&up[i];
  g.x = g.x / (1.f + __expf(-g.x)) * u.x;
  g.y = g.y / (1.f + __expf(-g.y)) * u.y;
  g.z = g.z / (1.f + __expf(-g.z)) * u.z;
  g.w = g.w / (1.f + __expf(-g.w)) * u.w;
  *(float4*)&gate[i] = g;
}

// ---------------------------------------------------------------------------
// Launch pipeline
// ---------------------------------------------------------------------------
extern "C" void kernel_launch(void* const* d_in, const int* in_sizes, int n_in,
                              void* d_out, int out_size) {
  const float* hidden = (const float*)d_in[0];
  const float* ln1 = (const float*)d_in[1];
  const float* ln2 = (const float*)d_in[2];
  const float* q_Us = (const float*)d_in[3];
  const float* q_V  = (const float*)d_in[4];
  const float* k_Us = (const float*)d_in[5];
  const float* k_V  = (const float*)d_in[6];
  const float* v_Us = (const float*)d_in[7];
  const float* v_V  = (const float*)d_in[8];
  const float* o_Us = (const float*)d_in[9];
  const float* o_V  = (const float*)d_in[10];
  const float* g_Us = (const float*)d_in[11];
  const float* g_V  = (const float*)d_in[12];
  const float* u_Us = (const float*)d_in[13];
  const float* u_V  = (const float*)d_in[14];
  const float* d_Us = (const float*)d_in[15];
  const float* d_V  = (const float*)d_in[16];
  float* out = (float*)d_out;

  Scratch* s = nullptr;
  cudaGetSymbolAddress((void**)&s, g_scratch);

  const int faSmem = FA_SMEM_FLOATS * 4;
  cudaFuncSetAttribute(flash_attn_tf32,
                       cudaFuncAttributeMaxDynamicSharedMemorySize, faSmem);

  rmsnorm_kernel<<<CT, 256>>>(hidden, ln1, s->x);

  gemm_tf32<<<dim3(8, 16, 1), 256>>>(s->x, q_V, nullptr, s->Pq,
                                     nullptr, nullptr, nullptr, nullptr,
                                     1024, CD);
  gemm_tf32<<<dim3(2, 16, 2), 256>>>(s->x, k_V, nullptr, s->Pk,
                                     s->x, v_V, nullptr, s->Pv, 256, CD);

  proj_us_rope<<<dim3(CT / 32, CH), dim3(32, 8)>>>(s->Pq, q_Us, s->q, CH, 1);
  proj_us_rope<<<dim3(CT / 32, CHK), dim3(32, 8)>>>(s->Pk, k_Us, s->k, CHK, 1);
  proj_us_rope<<<dim3(CT / 32, CHK), dim3(32, 8)>>>(s->Pv, v_Us, s->v, CHK, 0);

  flash_attn_tf32<<<dim3(CT / 64, CH), 256, faSmem>>>(s->q, s->k, s->v, s->attn);

  gemm_tf32<<<dim3(4, 16, 1), 256>>>(s->attn, o_V, nullptr, s->Po,
                                     nullptr, nullptr, nullptr, nullptr,
                                     512, CD);
  gemm_tf32<<<dim3(16, 16, 1), 256>>>(s->Po, o_Us, hidden, s->h,
                                      nullptr, nullptr, nullptr, nullptr,
                                      CD, 512);

  rmsnorm_kernel<<<CT, 256>>>(s->h, ln2, s->x);
  gemm_tf32<<<dim3(4, 16, 2), 256>>>(s->x, g_V, nullptr, s->Pg,
                                     s->x, u_V, nullptr, s->Pu, 512, CD);
  gemm_tf32<<<dim3(64, 16, 2), 256>>>(s->Pg, g_Us, nullptr, s->gate,
                                      s->Pu, u_Us, nullptr, s->up,
                                      CINTER, 512);
  silu_mul_kernel<<<(CT * CINTER / 4) / 256, 256>>>(s->gate, s->up);
  gemm_tf32<<<dim3(4, 16, 1), 256>>>(s->gate, d_V, nullptr, s->Pd,
                                     nullptr, nullptr, nullptr, nullptr,
                                     512, CINTER);
  gemm_tf32<<<dim3(16, 16, 1), 256>>>(s->Pd, d_Us, s->h, out,
                                      nullptr, nullptr, nullptr, nullptr,
                                      CD, 512);
}

// round 4
// speedup vs baseline: 5.0493x; 1.5000x over previous
#include <cuda_runtime.h>
#include <cuda_bf16.h>
#include <math.h>
#include <cstdint>

// ---------------------------------------------------------------------------
// Problem constants (B=1)
// ---------------------------------------------------------------------------
#define CT 2048      // tokens
#define CD 2048      // model dim
#define CH 32        // q heads
#define CHK 8        // kv heads
#define CDH 64       // head dim
#define CINTER 8192  // ffn inner

typedef __nv_bfloat16 bf16;
typedef __nv_bfloat162 bf162;

// ---------------------------------------------------------------------------
// Static device scratch
// ---------------------------------------------------------------------------
struct alignas(256) Scratch {
  // fp32
  float Pq[CT * (CH * 32)];
  float Pk[CT * (CHK * 32)];
  float Pv[CT * (CHK * 32)];
  float q[CH * CT * CDH];
  float k[CHK * CT * CDH];
  float v[CHK * CT * CDH];
  float h[CT * CD];
  // bf16 activations
  bf16 x[CT * CD];
  bf16 attn[CT * CD];
  bf16 Po[CT * 512];
  bf16 Pg[CT * 512];
  bf16 Pu[CT * 512];
  bf16 gate[CT * CINTER];
  bf16 up[CT * CINTER];
  bf16 Pd[CT * 512];
  // bf16 weights
  bf16 qV[1024 * CD];
  bf16 kV[256 * CD];
  bf16 vV[256 * CD];
  bf16 oUs[CD * 512];
  bf16 oV[512 * CD];
  bf16 gUs[CINTER * 512];
  bf16 gV[512 * CD];
  bf16 uUs[CINTER * 512];
  bf16 uV[512 * CD];
  bf16 dUs[CD * 512];
  bf16 dV[512 * CINTER];
};
__device__ Scratch g_scratch;

// ---------------------------------------------------------------------------
// helpers
// ---------------------------------------------------------------------------
__device__ __forceinline__ uint32_t f2tf(float x) {
  uint32_t r;
  asm("cvt.rna.tf32.f32 %0, %1;" : "=r"(r) : "f"(x));
  return r;
}
__device__ __forceinline__ void cp16(void* s, const void* g) {
  uint32_t sa = (uint32_t)__cvta_generic_to_shared(s);
  asm volatile("cp.async.cg.shared.global [%0], [%1], 16;" ::"r"(sa), "l"(g));
}
__device__ __forceinline__ void mma_tf32(float* c, const uint32_t* a,
                                         const uint32_t* b) {
  asm volatile(
      "mma.sync.aligned.m16n8k8.row.col.f32.tf32.tf32.f32 "
      "{%0,%1,%2,%3}, {%4,%5,%6,%7}, {%8,%9}, {%0,%1,%2,%3};"
      : "+f"(c[0]), "+f"(c[1]), "+f"(c[2]), "+f"(c[3])
      : "r"(a[0]), "r"(a[1]), "r"(a[2]), "r"(a[3]), "r"(b[0]), "r"(b[1]));
}
__device__ __forceinline__ void mma_bf16(float* c, const uint32_t* a,
                                         const uint32_t* b) {
  asm volatile(
      "mma.sync.aligned.m16n8k16.row.col.f32.bf16.bf16.f32 "
      "{%0,%1,%2,%3}, {%4,%5,%6,%7}, {%8,%9}, {%0,%1,%2,%3};"
      : "+f"(c[0]), "+f"(c[1]), "+f"(c[2]), "+f"(c[3])
      : "r"(a[0]), "r"(a[1]), "r"(a[2]), "r"(a[3]), "r"(b[0]), "r"(b[1]));
}
__device__ __forceinline__ void ldm4(uint32_t* r, const void* p) {
  uint32_t a = (uint32_t)__cvta_generic_to_shared(p);
  asm volatile(
      "ldmatrix.sync.aligned.m8n8.x4.shared.b16 {%0,%1,%2,%3}, [%4];"
      : "=r"(r[0]), "=r"(r[1]), "=r"(r[2]), "=r"(r[3])
      : "r"(a));
}

// ---------------------------------------------------------------------------
// weight conversion fp32 -> bf16 (11 arrays in one launch)
// ---------------------------------------------------------------------------
#define NCVT 11
struct CvtPack {
  const float* src[NCVT];
  bf16* dst[NCVT];
  int n4[NCVT];  // float4 count per segment
};
__global__ void cvt_f2bf(CvtPack p, int total4) {
  int i = blockIdx.x * 256 + threadIdx.x;
  if (i >= total4) return;
  int s = 0, off = i;
  while (off >= p.n4[s]) { off -= p.n4[s]; s++; }
  const float4 v = ((const float4*)p.src[s])[off];
  bf162* d = (bf162*)p.dst[s];
  d[off * 2] = __floats2bfloat162_rn(v.x, v.y);
  d[off * 2 + 1] = __floats2bfloat162_rn(v.z, v.w);
}

// ---------------------------------------------------------------------------
// RMSNorm (fp32 in, bf16 out)
// ---------------------------------------------------------------------------
__global__ void rmsnorm_bf(const float* __restrict__ in,
                           const float* __restrict__ w,
                           bf16* __restrict__ out) {
  const int t = blockIdx.x;
  const float* row = in + (size_t)t * CD;
  float ss = 0.f;
  for (int i = threadIdx.x; i < CD; i += 256) {
    float v = row[i];
    ss += v * v;
  }
  __shared__ float red[8];
#pragma unroll
  for (int o = 16; o > 0; o >>= 1) ss += __shfl_xor_sync(0xffffffffu, ss, o);
  if ((threadIdx.x & 31) == 0) red[threadIdx.x >> 5] = ss;
  __syncthreads();
  if (threadIdx.x == 0) {
    float v = 0.f;
#pragma unroll
    for (int i = 0; i < 8; i++) v += red[i];
    red[0] = v;
  }
  __syncthreads();
  const float inv = rsqrtf(red[0] * (1.0f / CD) + 1e-5f);
  for (int i = threadIdx.x * 2; i < CD; i += 512) {
    bf162 o = __floats2bfloat162_rn(row[i] * inv * w[i],
                                    row[i + 1] * inv * w[i + 1]);
    *(bf162*)&out[(size_t)t * CD + i] = o;
  }
}

// ---------------------------------------------------------------------------
// bf16 tensor-core GEMM (NT): C = A * B^T (+res fp32). 128x128x32 tiles.
// A[M,K] bf16 row-major, B[N,K] bf16 row-major. OB: bf16 output else fp32.
// blockIdx.z selects second paired problem.
// ---------------------------------------------------------------------------
template <bool OB>
__global__ __launch_bounds__(256, 2) void gemm_bf(
    const bf16* __restrict__ A1, const bf16* __restrict__ B1,
    const float* __restrict__ res1, void* __restrict__ C1,
    const bf16* __restrict__ A2, const bf16* __restrict__ B2,
    const float* __restrict__ res2, void* __restrict__ C2, int N, int K) {
  const bf16* A = blockIdx.z ? A2 : A1;
  const bf16* B = blockIdx.z ? B2 : B1;
  const float* res = blockIdx.z ? res2 : res1;
  void* C = blockIdx.z ? C2 : C1;

  __shared__ bf16 As[2][128][40];
  __shared__ bf16 Bs[2][128][40];

  const int tid = threadIdx.x;
  const int lane = tid & 31, warp = tid >> 5;
  const int wm = (warp & 1) * 64, wn = (warp >> 1) * 32;
  const int bm = blockIdx.y * 128, bn = blockIdx.x * 128;
  const int gi = lane >> 2, ti = lane & 3;
  const int grow = tid >> 1;
  const int gcol = (tid & 1) * 16;

  float acc[4][4][4];
#pragma unroll
  for (int i = 0; i < 4; i++)
#pragma unroll
    for (int j = 0; j < 4; j++)
#pragma unroll
      for (int l = 0; l < 4; l++) acc[i][j][l] = 0.f;

  const int nt = K >> 5;
  {
    const bf16* ga = &A[(size_t)(bm + grow) * K + gcol];
    cp16(&As[0][grow][gcol], ga);
    cp16(&As[0][grow][gcol + 8], ga + 8);
    const bf16* gb = &B[(size_t)(bn + grow) * K + gcol];
    cp16(&Bs[0][grow][gcol], gb);
    cp16(&Bs[0][grow][gcol + 8], gb + 8);
    asm volatile("cp.async.commit_group;" ::: "memory");
  }

  // ldmatrix address precompute
  const int arow = wm + (lane & 15);
  const int acol = (lane >> 4) * 8;
  const int g8 = lane >> 3;
  const int brow = wn + (g8 >> 1) * 8 + (lane & 7);
  const int bcol = (g8 & 1) * 8;

  for (int t = 0; t < nt; t++) {
    const int buf = t & 1;
    if (t + 1 < nt) {
      const int k0 = (t + 1) << 5;
      const bf16* ga = &A[(size_t)(bm + grow) * K + k0 + gcol];
      cp16(&As[buf ^ 1][grow][gcol], ga);
      cp16(&As[buf ^ 1][grow][gcol + 8], ga + 8);
      const bf16* gb = &B[(size_t)(bn + grow) * K + k0 + gcol];
      cp16(&Bs[buf ^ 1][grow][gcol], gb);
      cp16(&Bs[buf ^ 1][grow][gcol + 8], gb + 8);
      asm volatile("cp.async.commit_group;" ::: "memory");
      asm volatile("cp.async.wait_group 1;" ::: "memory");
    } else {
      asm volatile("cp.async.wait_group 0;" ::: "memory");
    }
    __syncthreads();

#pragma unroll
    for (int ks = 0; ks < 2; ks++) {
      uint32_t a[4][4], b[2][4];
#pragma unroll
      for (int fm = 0; fm < 4; fm++)
        ldm4(a[fm], &As[buf][arow + fm * 16][ks * 16 + acol]);
      ldm4(b[0], &Bs[buf][brow][ks * 16 + bcol]);
      ldm4(b[1], &Bs[buf][brow + 16][ks * 16 + bcol]);
#pragma unroll
      for (int fm = 0; fm < 4; fm++)
#pragma unroll
        for (int fn = 0; fn < 4; fn++)
          mma_bf16(acc[fm][fn], a[fm], &b[fn >> 1][(fn & 1) * 2]);
    }
    __syncthreads();
  }

#pragma unroll
  for (int fm = 0; fm < 4; fm++) {
#pragma unroll
    for (int fn = 0; fn < 4; fn++) {
      const int r = bm + wm + fm * 16 + gi;
      const int c = bn + wn + fn * 8 + ti * 2;
      if (OB) {
        bf16* Cb = (bf16*)C;
        *(bf162*)&Cb[(size_t)r * N + c] =
            __floats2bfloat162_rn(acc[fm][fn][0], acc[fm][fn][1]);
        *(bf162*)&Cb[(size_t)(r + 8) * N + c] =
            __floats2bfloat162_rn(acc[fm][fn][2], acc[fm][fn][3]);
      } else {
        float* Cf = (float*)C;
        float2 v0 = make_float2(acc[fm][fn][0], acc[fm][fn][1]);
        float2 v1 = make_float2(acc[fm][fn][2], acc[fm][fn][3]);
        if (res) {
          const float2 r0 = *(const float2*)&res[(size_t)r * N + c];
          const float2 r1 = *(const float2*)&res[(size_t)(r + 8) * N + c];
          v0.x += r0.x; v0.y += r0.y;
          v1.x += r1.x; v1.y += r1.y;
        }
        *(float2*)&Cf[(size_t)r * N + c] = v0;
        *(float2*)&Cf[(size_t)(r + 8) * N + c] = v1;
      }
    }
  }
}

// ---------------------------------------------------------------------------
// Per-head Us projection (rank 32 -> 64) + optional RoPE (fp32 path).
// ---------------------------------------------------------------------------
__global__ void proj_us_rope(const float* __restrict__ P,
                             const float* __restrict__ Us,
                             float* __restrict__ out, int nheads, int doRope) {
  const int hh = blockIdx.y;
  const int tg = threadIdx.y;
  const int dh = threadIdx.x;
  const int t0 = blockIdx.x * 32 + tg * 4;
  __shared__ float sUs[64][33];
  __shared__ float sP[32][33];
  const int tid = tg * 32 + dh;
  const float* UsH = Us + (size_t)hh * 64 * 32;
#pragma unroll
  for (int i = tid; i < 64 * 32; i += 256) sUs[i >> 5][i & 31] = UsH[i];
#pragma unroll
  for (int j = 0; j < 4; j++)
    sP[tg * 4 + j][dh] = P[(size_t)(t0 + j) * (nheads * 32) + hh * 32 + dh];
  __syncthreads();
  float x1[4] = {0.f, 0.f, 0.f, 0.f}, x2[4] = {0.f, 0.f, 0.f, 0.f};
#pragma unroll
  for (int r = 0; r < 32; r++) {
    const float u1 = sUs[dh][r];
    const float u2 = sUs[dh + 32][r];
#pragma unroll
    for (int j = 0; j < 4; j++) {
      const float p = sP[tg * 4 + j][r];
      x1[j] = fmaf(p, u1, x1[j]);
      x2[j] = fmaf(p, u2, x2[j]);
    }
  }
  float sn = 0.f, cs = 1.f;
  const float invf = exp2f(-0.41524101186092028f * (float)dh);
#pragma unroll
  for (int j = 0; j < 4; j++) {
    float o1 = x1[j], o2 = x2[j];
    if (doRope) {
      sincosf((float)(t0 + j) * invf, &sn, &cs);
      o1 = x1[j] * cs - x2[j] * sn;
      o2 = x2[j] * cs + x1[j] * sn;
    }
    const size_t base = ((size_t)hh * CT + t0 + j) * CDH;
    out[base + dh] = o1;
    out[base + dh + 32] = o2;
  }
}

// ---------------------------------------------------------------------------
// tf32 causal flash attention (fp32 in, bf16 out). 64x64 tiles, GQA rep 4.
// ---------------------------------------------------------------------------
#define FTS 68
#define FA_SMEM_FLOATS (4 * 64 * FTS + 64 * 3 + 64 * 4)
__global__ __launch_bounds__(256) void flash_attn_tf32(
    const float* __restrict__ Q, const float* __restrict__ Kg,
    const float* __restrict__ Vg, bf16* __restrict__ Og) {
  extern __shared__ float sm[];
  float* Qs = sm;
  float* Ks = Qs + 64 * FTS;
  float* Vt = Ks + 64 * FTS;
  float* Ps = Vt + 64 * FTS;
  float* mrow = Ps + 64 * FTS;
  float* lrow = mrow + 64;
  float* arow = lrow + 64;
  float* redm = arow + 64;
  float* redl = redm + 128;

  const int qb = blockIdx.x, hh = blockIdx.y, hk = hh >> 2;
  const int tid = threadIdx.x;
  const int lane = tid & 31, warp = tid >> 5;
  const int gi = lane >> 2, ti = lane & 3;
  const int wm = (warp >> 1) * 16;
  const int wn = (warp & 1) * 32;
  const int ldr = tid >> 2, ldd = (tid & 3) * 16;

  {
    const float* qg = Q + ((size_t)hh * CT + qb * 64 + ldr) * 64 + ldd;
#pragma unroll
    for (int j = 0; j < 16; j += 4)
      *(float4*)&Qs[ldr * FTS + ldd + j] = *(const float4*)(qg + j);
  }
  if (tid < 64) { mrow[tid] = -1e30f; lrow[tid] = 0.f; }

  float oacc[4][4];
#pragma unroll
  for (int i = 0; i < 4; i++)
#pragma unroll
    for (int j = 0; j < 4; j++) oacc[i][j] = 0.f;

  for (int kb = 0; kb <= qb; kb++) {
    __syncthreads();
    {
      const float* kg = Kg + ((size_t)hk * CT + kb * 64 + ldr) * 64 + ldd;
      const float* vg = Vg + ((size_t)hk * CT + kb * 64 + ldr) * 64 + ldd;
#pragma unroll
      for (int j = 0; j < 16; j += 4) {
        *(float4*)&Ks[ldr * FTS + ldd + j] = *(const float4*)(kg + j);
        const float4 v4 = *(const float4*)(vg + j);
        Vt[(ldd + j + 0) * FTS + ldr] = v4.x;
        Vt[(ldd + j + 1) * FTS + ldr] = v4.y;
        Vt[(ldd + j + 2) * FTS + ldr] = v4.z;
        Vt[(ldd + j + 3) * FTS + ldr] = v4.w;
      }
    }
    __syncthreads();

    float sacc[4][4];
#pragma unroll
    for (int i = 0; i < 4; i++)
#pragma unroll
      for (int j = 0; j < 4; j++) sacc[i][j] = 0.f;
#pragma unroll
    for (int ks = 0; ks < 8; ks++) {
      const int kc = ks * 8 + ti;
      uint32_t a[4], b[4][2];
      a[0] = f2tf(Qs[(wm + gi) * FTS + kc]);
      a[1] = f2tf(Qs[(wm + gi + 8) * FTS + kc]);
      a[2] = f2tf(Qs[(wm + gi) * FTS + kc + 4]);
      a[3] = f2tf(Qs[(wm + gi + 8) * FTS + kc + 4]);
#pragma unroll
      for (int fn = 0; fn < 4; fn++) {
        b[fn][0] = f2tf(Ks[(wn + fn * 8 + gi) * FTS + kc]);
        b[fn][1] = f2tf(Ks[(wn + fn * 8 + gi) * FTS + kc + 4]);
      }
#pragma unroll
      for (int fn = 0; fn < 4; fn++) mma_tf32(sacc[fn], a, b[fn]);
    }

    const bool diag = (kb == qb);
    float rmax0 = -1e30f, rmax1 = -1e30f;
#pragma unroll
    for (int fn = 0; fn < 4; fn++) {
      const int c = wn + fn * 8 + 2 * ti;
#pragma unroll
      for (int l = 0; l < 4; l++) {
        float v = sacc[fn][l] * 0.125f;
        const int row = wm + gi + ((l >= 2) ? 8 : 0);
        const int col = c + (l & 1);
        if (diag && col > row) v = -1e30f;
        sacc[fn][l] = v;
        if (l >= 2) rmax1 = fmaxf(rmax1, v);
        else rmax0 = fmaxf(rmax0, v);
      }
    }
    rmax0 = fmaxf(rmax0, __shfl_xor_sync(0xffffffffu, rmax0, 1));
    rmax0 = fmaxf(rmax0, __shfl_xor_sync(0xffffffffu, rmax0, 2));
    rmax1 = fmaxf(rmax1, __shfl_xor_sync(0xffffffffu, rmax1, 1));
    rmax1 = fmaxf(rmax1, __shfl_xor_sync(0xffffffffu, rmax1, 2));
    if (ti == 0) {
      redm[(wm + gi) * 2 + (warp & 1)] = rmax0;
      redm[(wm + gi + 8) * 2 + (warp & 1)] = rmax1;
    }
    __syncthreads();
    if (tid < 64) {
      const float mold = mrow[tid];
      const float mnew = fmaxf(mold, fmaxf(redm[tid * 2], redm[tid * 2 + 1]));
      const float al = __expf(mold - mnew);
      mrow[tid] = mnew; arow[tid] = al; lrow[tid] *= al;
    }
    __syncthreads();

    const float m0 = mrow[wm + gi], m1 = mrow[wm + gi + 8];
    const float a0 = arow[wm + gi], a1 = arow[wm + gi + 8];
    float rs0 = 0.f, rs1 = 0.f;
#pragma unroll
    for (int fn = 0; fn < 4; fn++) {
      const int c = wn + fn * 8 + 2 * ti;
      const float p00 = __expf(sacc[fn][0] - m0);
      const float p01 = __expf(sacc[fn][1] - m0);
      const float p10 = __expf(sacc[fn][2] - m1);
      const float p11 = __expf(sacc[fn][3] - m1);
      rs0 += p00 + p01; rs1 += p10 + p11;
      *(float2*)&Ps[(wm + gi) * FTS + c] = make_float2(p00, p01);
      *(float2*)&Ps[(wm + gi + 8) * FTS + c] = make_float2(p10, p11);
    }
    rs0 += __shfl_xor_sync(0xffffffffu, rs0, 1);
    rs0 += __shfl_xor_sync(0xffffffffu, rs0, 2);
    rs1 += __shfl_xor_sync(0xffffffffu, rs1, 1);
    rs1 += __shfl_xor_sync(0xffffffffu, rs1, 2);
    if (ti == 0) {
      redl[(wm + gi) * 2 + (warp & 1)] = rs0;
      redl[(wm + gi + 8) * 2 + (warp & 1)] = rs1;
    }
#pragma unroll
    for (int fn = 0; fn < 4; fn++) {
      oacc[fn][0] *= a0; oacc[fn][1] *= a0;
      oacc[fn][2] *= a1; oacc[fn][3] *= a1;
    }
    __syncthreads();
    if (tid < 64) lrow[tid] += redl[tid * 2] + redl[tid * 2 + 1];

#pragma unroll
    for (int ks = 0; ks < 8; ks++) {
      const int kc = ks * 8 + ti;
      uint32_t a[4], b[4][2];
      a[0] = f2tf(Ps[(wm + gi) * FTS + kc]);
      a[1] = f2tf(Ps[(wm + gi + 8) * FTS + kc]);
      a[2] = f2tf(Ps[(wm + gi) * FTS + kc + 4]);
      a[3] = f2tf(Ps[(wm + gi + 8) * FTS + kc + 4]);
#pragma unroll
      for (int fn = 0; fn < 4; fn++) {
        b[fn][0] = f2tf(Vt[(wn + fn * 8 + gi) * FTS + kc]);
        b[fn][1] = f2tf(Vt[(wn + fn * 8 + gi) * FTS + kc + 4]);
      }
#pragma unroll
      for (int fn = 0; fn < 4; fn++) mma_tf32(oacc[fn], a, b[fn]);
    }
  }
  __syncthreads();

  const float inv0 = 1.f / lrow[wm + gi];
  const float inv1 = 1.f / lrow[wm + gi + 8];
#pragma unroll
  for (int fn = 0; fn < 4; fn++) {
    const int col = hh * 64 + wn + fn * 8 + 2 * ti;
    *(bf162*)&Og[(size_t)(qb * 64 + wm + gi) * CD + col] =
        __floats2bfloat162_rn(oacc[fn][0] * inv0, oacc[fn][1] * inv0);
    *(bf162*)&Og[(size_t)(qb * 64 + wm + gi + 8) * CD + col] =
        __floats2bfloat162_rn(oacc[fn][2] * inv1, oacc[fn][3] * inv1);
  }
}

// ---------------------------------------------------------------------------
// act = silu(gate) * up  (bf16 in/out, in place into gate)
// ---------------------------------------------------------------------------
__global__ void silu_mul_bf(bf16* __restrict__ gate,
                            const bf16* __restrict__ up) {
  const size_t i = ((size_t)blockIdx.x * 256 + threadIdx.x) * 4;
  bf162 g0 = *(bf162*)&gate[i];
  bf162 g1 = *(bf162*)&gate[i + 2];
  const bf162 u0 = *(const bf162*)&up[i];
  const bf162 u1 = *(const bf162*)&up[i + 2];
  float a = __bfloat162float(g0.x), b = __bfloat162float(g0.y);
  float c = __bfloat162float(g1.x), d = __bfloat162float(g1.y);
  a = a / (1.f + __expf(-a)) * __bfloat162float(u0.x);
  b = b / (1.f + __expf(-b)) * __bfloat162float(u0.y);
  c = c / (1.f + __expf(-c)) * __bfloat162float(u1.x);
  d = d / (1.f + __expf(-d)) * __bfloat162float(u1.y);
  *(bf162*)&gate[i] = __floats2bfloat162_rn(a, b);
  *(bf162*)&gate[i + 2] = __floats2bfloat162_rn(c, d);
}

// ---------------------------------------------------------------------------
// Launch pipeline
// ---------------------------------------------------------------------------
extern "C" void kernel_launch(void* const* d_in, const int* in_sizes, int n_in,
                              void* d_out, int out_size) {
  const float* hidden = (const float*)d_in[0];
  const float* ln1 = (const float*)d_in[1];
  const float* ln2 = (const float*)d_in[2];
  const float* q_Us = (const float*)d_in[3];
  const float* q_V  = (const float*)d_in[4];
  const float* k_Us = (const float*)d_in[5];
  const float* k_V  = (const float*)d_in[6];
  const float* v_Us = (const float*)d_in[7];
  const float* v_V  = (const float*)d_in[8];
  const float* o_Us = (const float*)d_in[9];
  const float* o_V  = (const float*)d_in[10];
  const float* g_Us = (const float*)d_in[11];
  const float* g_V  = (const float*)d_in[12];
  const float* u_Us = (const float*)d_in[13];
  const float* u_V  = (const float*)d_in[14];
  const float* d_Us = (const float*)d_in[15];
  const float* d_V  = (const float*)d_in[16];
  float* out = (float*)d_out;

  Scratch* s = nullptr;
  cudaGetSymbolAddress((void**)&s, g_scratch);

  const int faSmem = FA_SMEM_FLOATS * 4;
  cudaFuncSetAttribute(flash_attn_tf32,
                       cudaFuncAttributeMaxDynamicSharedMemorySize, faSmem);

  // 0. convert weights to bf16 (one launch)
  {
    CvtPack p;
    const float* srcs[NCVT] = {q_V, k_V, v_V, o_Us, o_V, g_Us,
                               g_V, u_Us, u_V, d_Us, d_V};
    bf16* dsts[NCVT] = {s->qV, s->kV, s->vV, s->oUs, s->oV, s->gUs,
                        s->gV, s->uUs, s->uV, s->dUs, s->dV};
    const int ns[NCVT] = {1024 * CD, 256 * CD, 256 * CD, CD * 512, 512 * CD,
                          CINTER * 512, 512 * CD, CINTER * 512, 512 * CD,
                          CD * 512, 512 * CINTER};
    int total4 = 0;
    for (int i = 0; i < NCVT; i++) {
      p.src[i] = srcs[i]; p.dst[i] = dsts[i]; p.n4[i] = ns[i] / 4;
      total4 += ns[i] / 4;
    }
    cvt_f2bf<<<(total4 + 255) / 256, 256>>>(p, total4);
  }

  // 1. x = rmsnorm(hidden, ln1) -> bf16
  rmsnorm_bf<<<CT, 256>>>(hidden, ln1, s->x);

  // 2. low-rank down-projections (fp32 out for rope path)
  gemm_bf<false><<<dim3(8, 16, 1), 256>>>(s->x, s->qV, nullptr, s->Pq,
                                          nullptr, nullptr, nullptr, nullptr,
                                          1024, CD);
  gemm_bf<false><<<dim3(2, 16, 2), 256>>>(s->x, s->kV, nullptr, s->Pk,
                                          s->x, s->vV, nullptr, s->Pv,
                                          256, CD);

  // 3. Us up-projections + RoPE
  proj_us_rope<<<dim3(CT / 32, CH), dim3(32, 8)>>>(s->Pq, q_Us, s->q, CH, 1);
  proj_us_rope<<<dim3(CT / 32, CHK), dim3(32, 8)>>>(s->Pk, k_Us, s->k, CHK, 1);
  proj_us_rope<<<dim3(CT / 32, CHK), dim3(32, 8)>>>(s->Pv, v_Us, s->v, CHK, 0);

  // 4. attention -> bf16
  flash_attn_tf32<<<dim3(CT / 64, CH), 256, faSmem>>>(s->q, s->k, s->v,
                                                      s->attn);

  // 5. output projection + residual -> h (fp32)
  gemm_bf<true><<<dim3(4, 16, 1), 256>>>(s->attn, s->oV, nullptr, s->Po,
                                         nullptr, nullptr, nullptr, nullptr,
                                         512, CD);
  gemm_bf<false><<<dim3(16, 16, 1), 256>>>(s->Po, s->oUs, hidden, s->h,
                                           nullptr, nullptr, nullptr, nullptr,
                                           CD, 512);

  // 6. FFN
  rmsnorm_bf<<<CT, 256>>>(s->h, ln2, s->x);
  gemm_bf<true><<<dim3(4, 16, 2), 256>>>(s->x, s->gV, nullptr, s->Pg,
                                         s->x, s->uV, nullptr, s->Pu,
                                         512, CD);
  gemm_bf<true><<<dim3(64, 16, 2), 256>>>(s->Pg, s->gUs, nullptr, s->gate,
                                          s->Pu, s->uUs, nullptr, s->up,
                                          CINTER, 512);
  silu_mul_bf<<<(CT * CINTER / 4) / 256, 256>>>(s->gate, s->up);
  gemm_bf<true><<<dim3(4, 16, 1), 256>>>(s->gate, s->dV, nullptr, s->Pd,
                                         nullptr, nullptr, nullptr, nullptr,
                                         512, CINTER);
  gemm_bf<false><<<dim3(16, 16, 1), 256>>>(s->Pd, s->dUs, s->h, out,
                                           nullptr, nullptr, nullptr, nullptr,
                                           CD, 512);
}

// round 5
// speedup vs baseline: 7.1061x; 1.4073x over previous
#include <cuda_runtime.h>
#include <cuda_bf16.h>
#include <math.h>
#include <cstdint>

// ---------------------------------------------------------------------------
// Problem constants (B=1)
// ---------------------------------------------------------------------------
#define CT 2048      // tokens
#define CD 2048      // model dim
#define CH 32        // q heads
#define CHK 8        // kv heads
#define CDH 64       // head dim
#define CINTER 8192  // ffn inner

typedef __nv_bfloat16 bf16;
typedef __nv_bfloat162 bf162;

// ---------------------------------------------------------------------------
// Static device scratch
// ---------------------------------------------------------------------------
struct alignas(256) Scratch {
  // fp32
  float Pqkv[CT * 1536];       // packed q|k|v low-rank projections
  float h[CT * CD];
  float skpart[4 * CT * 512];  // split-K partials
  // bf16 activations
  bf16 x[CT * CD];
  bf16 q[CH * CT * CDH];
  bf16 k[CHK * CT * CDH];
  bf16 v[CHK * CT * CDH];
  bf16 attn[CT * CD];
  bf16 Po[CT * 512];
  bf16 Pg[CT * 512];
  bf16 Pu[CT * 512];
  bf16 gate[CT * CINTER];
  bf16 up[CT * CINTER];
  bf16 Pd[CT * 512];
  // bf16 weights (qV,kV,vV contiguous => packed [1536, CD])
  bf16 qV[1024 * CD];
  bf16 kV[256 * CD];
  bf16 vV[256 * CD];
  bf16 oUs[CD * 512];
  bf16 oV[512 * CD];
  bf16 gUs[CINTER * 512];
  bf16 gV[512 * CD];
  bf16 uUs[CINTER * 512];
  bf16 uV[512 * CD];
  bf16 dUs[CD * 512];
  bf16 dV[512 * CINTER];
};
__device__ Scratch g_scratch;

// ---------------------------------------------------------------------------
// helpers
// ---------------------------------------------------------------------------
__device__ __forceinline__ void cp16(void* s, const void* g) {
  uint32_t sa = (uint32_t)__cvta_generic_to_shared(s);
  asm volatile("cp.async.cg.shared.global [%0], [%1], 16;" ::"r"(sa), "l"(g));
}
__device__ __forceinline__ void mma_bf16(float* c, const uint32_t* a,
                                         const uint32_t* b) {
  asm volatile(
      "mma.sync.aligned.m16n8k16.row.col.f32.bf16.bf16.f32 "
      "{%0,%1,%2,%3}, {%4,%5,%6,%7}, {%8,%9}, {%0,%1,%2,%3};"
      : "+f"(c[0]), "+f"(c[1]), "+f"(c[2]), "+f"(c[3])
      : "r"(a[0]), "r"(a[1]), "r"(a[2]), "r"(a[3]), "r"(b[0]), "r"(b[1]));
}
__device__ __forceinline__ void ldm4(uint32_t* r, const void* p) {
  uint32_t a = (uint32_t)__cvta_generic_to_shared(p);
  asm volatile(
      "ldmatrix.sync.aligned.m8n8.x4.shared.b16 {%0,%1,%2,%3}, [%4];"
      : "=r"(r[0]), "=r"(r[1]), "=r"(r[2]), "=r"(r[3])
      : "r"(a));
}

// ---------------------------------------------------------------------------
// weight conversion fp32 -> bf16
// ---------------------------------------------------------------------------
#define NCVT 11
struct CvtPack {
  const float* src[NCVT];
  bf16* dst[NCVT];
  int n4[NCVT];
};
__global__ void cvt_f2bf(CvtPack p, int total4) {
  int i = blockIdx.x * 256 + threadIdx.x;
  if (i >= total4) return;
  int s = 0, off = i;
  while (off >= p.n4[s]) { off -= p.n4[s]; s++; }
  const float4 v = ((const float4*)p.src[s])[off];
  bf162* d = (bf162*)p.dst[s];
  d[off * 2] = __floats2bfloat162_rn(v.x, v.y);
  d[off * 2 + 1] = __floats2bfloat162_rn(v.z, v.w);
}

// ---------------------------------------------------------------------------
// RMSNorm (fp32 in, bf16 out)
// ---------------------------------------------------------------------------
__global__ void rmsnorm_bf(const float* __restrict__ in,
                           const float* __restrict__ w,
                           bf16* __restrict__ out) {
  const int t = blockIdx.x;
  const float* row = in + (size_t)t * CD;
  float ss = 0.f;
  for (int i = threadIdx.x; i < CD; i += 256) {
    float v = row[i];
    ss += v * v;
  }
  __shared__ float red[8];
#pragma unroll
  for (int o = 16; o > 0; o >>= 1) ss += __shfl_xor_sync(0xffffffffu, ss, o);
  if ((threadIdx.x & 31) == 0) red[threadIdx.x >> 5] = ss;
  __syncthreads();
  if (threadIdx.x == 0) {
    float v = 0.f;
#pragma unroll
    for (int i = 0; i < 8; i++) v += red[i];
    red[0] = v;
  }
  __syncthreads();
  const float inv = rsqrtf(red[0] * (1.0f / CD) + 1e-5f);
  for (int i = threadIdx.x * 2; i < CD; i += 512) {
    bf162 o = __floats2bfloat162_rn(row[i] * inv * w[i],
                                    row[i + 1] * inv * w[i + 1]);
    *(bf162*)&out[(size_t)t * CD + i] = o;
  }
}

// ---------------------------------------------------------------------------
// bf16 tensor-core GEMM (NT): C = A * B^T (+res fp32). 128x128x32 tiles.
// ---------------------------------------------------------------------------
template <bool OB>
__global__ __launch_bounds__(256, 2) void gemm_bf(
    const bf16* __restrict__ A1, const bf16* __restrict__ B1,
    const float* __restrict__ res1, void* __restrict__ C1,
    const bf16* __restrict__ A2, const bf16* __restrict__ B2,
    const float* __restrict__ res2, void* __restrict__ C2, int N, int K) {
  const bf16* A = blockIdx.z ? A2 : A1;
  const bf16* B = blockIdx.z ? B2 : B1;
  const float* res = blockIdx.z ? res2 : res1;
  void* C = blockIdx.z ? C2 : C1;

  __shared__ bf16 As[2][128][40];
  __shared__ bf16 Bs[2][128][40];

  const int tid = threadIdx.x;
  const int lane = tid & 31, warp = tid >> 5;
  const int wm = (warp & 1) * 64, wn = (warp >> 1) * 32;
  const int bm = blockIdx.y * 128, bn = blockIdx.x * 128;
  const int gi = lane >> 2, ti = lane & 3;
  const int grow = tid >> 1;
  const int gcol = (tid & 1) * 16;

  float acc[4][4][4];
#pragma unroll
  for (int i = 0; i < 4; i++)
#pragma unroll
    for (int j = 0; j < 4; j++)
#pragma unroll
      for (int l = 0; l < 4; l++) acc[i][j][l] = 0.f;

  const int nt = K >> 5;
  {
    const bf16* ga = &A[(size_t)(bm + grow) * K + gcol];
    cp16(&As[0][grow][gcol], ga);
    cp16(&As[0][grow][gcol + 8], ga + 8);
    const bf16* gb = &B[(size_t)(bn + grow) * K + gcol];
    cp16(&Bs[0][grow][gcol], gb);
    cp16(&Bs[0][grow][gcol + 8], gb + 8);
    asm volatile("cp.async.commit_group;" ::: "memory");
  }

  const int arow = wm + (lane & 15);
  const int acol = (lane >> 4) * 8;
  const int g8 = lane >> 3;
  const int brow = wn + (g8 >> 1) * 8 + (lane & 7);
  const int bcol = (g8 & 1) * 8;

  for (int t = 0; t < nt; t++) {
    const int buf = t & 1;
    if (t + 1 < nt) {
      const int k0 = (t + 1) << 5;
      const bf16* ga = &A[(size_t)(bm + grow) * K + k0 + gcol];
      cp16(&As[buf ^ 1][grow][gcol], ga);
      cp16(&As[buf ^ 1][grow][gcol + 8], ga + 8);
      const bf16* gb = &B[(size_t)(bn + grow) * K + k0 + gcol];
      cp16(&Bs[buf ^ 1][grow][gcol], gb);
      cp16(&Bs[buf ^ 1][grow][gcol + 8], gb + 8);
      asm volatile("cp.async.commit_group;" ::: "memory");
      asm volatile("cp.async.wait_group 1;" ::: "memory");
    } else {
      asm volatile("cp.async.wait_group 0;" ::: "memory");
    }
    __syncthreads();

#pragma unroll
    for (int ks = 0; ks < 2; ks++) {
      uint32_t a[4][4], b[2][4];
#pragma unroll
      for (int fm = 0; fm < 4; fm++)
        ldm4(a[fm], &As[buf][arow + fm * 16][ks * 16 + acol]);
      ldm4(b[0], &Bs[buf][brow][ks * 16 + bcol]);
      ldm4(b[1], &Bs[buf][brow + 16][ks * 16 + bcol]);
#pragma unroll
      for (int fm = 0; fm < 4; fm++)
#pragma unroll
        for (int fn = 0; fn < 4; fn++)
          mma_bf16(acc[fm][fn], a[fm], &b[fn >> 1][(fn & 1) * 2]);
    }
    __syncthreads();
  }

#pragma unroll
  for (int fm = 0; fm < 4; fm++) {
#pragma unroll
    for (int fn = 0; fn < 4; fn++) {
      const int r = bm + wm + fm * 16 + gi;
      const int c = bn + wn + fn * 8 + ti * 2;
      if (OB) {
        bf16* Cb = (bf16*)C;
        *(bf162*)&Cb[(size_t)r * N + c] =
            __floats2bfloat162_rn(acc[fm][fn][0], acc[fm][fn][1]);
        *(bf162*)&Cb[(size_t)(r + 8) * N + c] =
            __floats2bfloat162_rn(acc[fm][fn][2], acc[fm][fn][3]);
      } else {
        float* Cf = (float*)C;
        float2 v0 = make_float2(acc[fm][fn][0], acc[fm][fn][1]);
        float2 v1 = make_float2(acc[fm][fn][2], acc[fm][fn][3]);
        if (res) {
          const float2 r0 = *(const float2*)&res[(size_t)r * N + c];
          const float2 r1 = *(const float2*)&res[(size_t)(r + 8) * N + c];
          v0.x += r0.x; v0.y += r0.y;
          v1.x += r1.x; v1.y += r1.y;
        }
        *(float2*)&Cf[(size_t)r * N + c] = v0;
        *(float2*)&Cf[(size_t)(r + 8) * N + c] = v1;
      }
    }
  }
}

// ---------------------------------------------------------------------------
// split-K bf16 GEMM: partial C (fp32) per K-chunk; grid.z = chunk index.
// ---------------------------------------------------------------------------
__global__ __launch_bounds__(256, 2) void gemm_bf_sk(
    const bf16* __restrict__ A, const bf16* __restrict__ B,
    float* __restrict__ Cpart, int N, int K, int Kc) {
  __shared__ bf16 As[2][128][40];
  __shared__ bf16 Bs[2][128][40];

  const int tid = threadIdx.x;
  const int lane = tid & 31, warp = tid >> 5;
  const int wm = (warp & 1) * 64, wn = (warp >> 1) * 32;
  const int bm = blockIdx.y * 128, bn = blockIdx.x * 128;
  const int gi = lane >> 2, ti = lane & 3;
  const int grow = tid >> 1;
  const int gcol = (tid & 1) * 16;
  const int kbase = blockIdx.z * Kc;
  float* C = Cpart + (size_t)blockIdx.z * CT * N;

  float acc[4][4][4];
#pragma unroll
  for (int i = 0; i < 4; i++)
#pragma unroll
    for (int j = 0; j < 4; j++)
#pragma unroll
      for (int l = 0; l < 4; l++) acc[i][j][l] = 0.f;

  const int nt = Kc >> 5;
  {
    const bf16* ga = &A[(size_t)(bm + grow) * K + kbase + gcol];
    cp16(&As[0][grow][gcol], ga);
    cp16(&As[0][grow][gcol + 8], ga + 8);
    const bf16* gb = &B[(size_t)(bn + grow) * K + kbase + gcol];
    cp16(&Bs[0][grow][gcol], gb);
    cp16(&Bs[0][grow][gcol + 8], gb + 8);
    asm volatile("cp.async.commit_group;" ::: "memory");
  }

  const int arow = wm + (lane & 15);
  const int acol = (lane >> 4) * 8;
  const int g8 = lane >> 3;
  const int brow = wn + (g8 >> 1) * 8 + (lane & 7);
  const int bcol = (g8 & 1) * 8;

  for (int t = 0; t < nt; t++) {
    const int buf = t & 1;
    if (t + 1 < nt) {
      const int k0 = kbase + ((t + 1) << 5);
      const bf16* ga = &A[(size_t)(bm + grow) * K + k0 + gcol];
      cp16(&As[buf ^ 1][grow][gcol], ga);
      cp16(&As[buf ^ 1][grow][gcol + 8], ga + 8);
      const bf16* gb = &B[(size_t)(bn + grow) * K + k0 + gcol];
      cp16(&Bs[buf ^ 1][grow][gcol], gb);
      cp16(&Bs[buf ^ 1][grow][gcol + 8], gb + 8);
      asm volatile("cp.async.commit_group;" ::: "memory");
      asm volatile("cp.async.wait_group 1;" ::: "memory");
    } else {
      asm volatile("cp.async.wait_group 0;" ::: "memory");
    }
    __syncthreads();

#pragma unroll
    for (int ks = 0; ks < 2; ks++) {
      uint32_t a[4][4], b[2][4];
#pragma unroll
      for (int fm = 0; fm < 4; fm++)
        ldm4(a[fm], &As[buf][arow + fm * 16][ks * 16 + acol]);
      ldm4(b[0], &Bs[buf][brow][ks * 16 + bcol]);
      ldm4(b[1], &Bs[buf][brow + 16][ks * 16 + bcol]);
#pragma unroll
      for (int fm = 0; fm < 4; fm++)
#pragma unroll
        for (int fn = 0; fn < 4; fn++)
          mma_bf16(acc[fm][fn], a[fm], &b[fn >> 1][(fn & 1) * 2]);
    }
    __syncthreads();
  }

#pragma unroll
  for (int fm = 0; fm < 4; fm++) {
#pragma unroll
    for (int fn = 0; fn < 4; fn++) {
      const int r = bm + wm + fm * 16 + gi;
      const int c = bn + wn + fn * 8 + ti * 2;
      *(float2*)&C[(size_t)r * N + c] =
          make_float2(acc[fm][fn][0], acc[fm][fn][1]);
      *(float2*)&C[(size_t)(r + 8) * N + c] =
          make_float2(acc[fm][fn][2], acc[fm][fn][3]);
    }
  }
}

// reduce S split-K partials -> bf16
__global__ void reduce_sk(const float* __restrict__ part,
                          bf16* __restrict__ out, int MN, int S) {
  const int i = (blockIdx.x * 256 + threadIdx.x) * 4;
  if (i >= MN) return;
  float4 a = *(const float4*)&part[i];
  for (int s = 1; s < S; s++) {
    const float4 p = *(const float4*)&part[(size_t)s * MN + i];
    a.x += p.x; a.y += p.y; a.z += p.z; a.w += p.w;
  }
  *(bf162*)&out[i] = __floats2bfloat162_rn(a.x, a.y);
  *(bf162*)&out[i + 2] = __floats2bfloat162_rn(a.z, a.w);
}

// ---------------------------------------------------------------------------
// Per-head Us projection (rank 32 -> 64) + optional RoPE. fp32 in, bf16 out.
// ---------------------------------------------------------------------------
__global__ void proj_us_rope(const float* __restrict__ P,
                             const float* __restrict__ Us,
                             bf16* __restrict__ out, int pstride, int doRope) {
  const int hh = blockIdx.y;
  const int tg = threadIdx.y;
  const int dh = threadIdx.x;
  const int t0 = blockIdx.x * 32 + tg * 4;
  __shared__ float sUs[64][33];
  __shared__ float sP[32][33];
  const int tid = tg * 32 + dh;
  const float* UsH = Us + (size_t)hh * 64 * 32;
#pragma unroll
  for (int i = tid; i < 64 * 32; i += 256) sUs[i >> 5][i & 31] = UsH[i];
#pragma unroll
  for (int j = 0; j < 4; j++)
    sP[tg * 4 + j][dh] = P[(size_t)(t0 + j) * pstride + hh * 32 + dh];
  __syncthreads();
  float x1[4] = {0.f, 0.f, 0.f, 0.f}, x2[4] = {0.f, 0.f, 0.f, 0.f};
#pragma unroll
  for (int r = 0; r < 32; r++) {
    const float u1 = sUs[dh][r];
    const float u2 = sUs[dh + 32][r];
#pragma unroll
    for (int j = 0; j < 4; j++) {
      const float p = sP[tg * 4 + j][r];
      x1[j] = fmaf(p, u1, x1[j]);
      x2[j] = fmaf(p, u2, x2[j]);
    }
  }
  float sn = 0.f, cs = 1.f;
  const float invf = exp2f(-0.41524101186092028f * (float)dh);
#pragma unroll
  for (int j = 0; j < 4; j++) {
    float o1 = x1[j], o2 = x2[j];
    if (doRope) {
      sincosf((float)(t0 + j) * invf, &sn, &cs);
      o1 = x1[j] * cs - x2[j] * sn;
      o2 = x2[j] * cs + x1[j] * sn;
    }
    const size_t base = ((size_t)hh * CT + t0 + j) * CDH;
    out[base + dh] = __float2bfloat16(o1);
    out[base + dh + 32] = __float2bfloat16(o2);
  }
}

// ---------------------------------------------------------------------------
// bf16 causal flash attention. 64x64 tiles, Dh=64, GQA rep 4.
// 8 warps: wm=(warp>>1)*16 rows, wn=(warp&1)*32 cols. mma m16n8k16.
// ---------------------------------------------------------------------------
#define FTS2 72
#define FA_SMEM_BYTES (4 * 64 * FTS2 * 2 + (64 * 3 + 128 * 2) * 4)
__global__ __launch_bounds__(256) void flash_attn_bf(
    const bf16* __restrict__ Q, const bf16* __restrict__ Kg,
    const bf16* __restrict__ Vg, bf16* __restrict__ Og) {
  extern __shared__ char smb[];
  bf16* Qs = (bf16*)smb;                 // [64][FTS2]
  bf16* Ks = Qs + 64 * FTS2;             // [64][FTS2]
  bf16* Vt = Ks + 64 * FTS2;             // [d][kk]
  bf16* Ps = Vt + 64 * FTS2;             // [q][kk]
  float* mrow = (float*)(Ps + 64 * FTS2);
  float* lrow = mrow + 64;
  float* arow = lrow + 64;
  float* redm = arow + 64;               // [64][2]
  float* redl = redm + 128;              // [64][2]

  const int qb = blockIdx.x, hh = blockIdx.y, hk = hh >> 2;
  const int tid = threadIdx.x;
  const int lane = tid & 31, warp = tid >> 5;
  const int gi = lane >> 2, ti = lane & 3;
  const int wm = (warp >> 1) * 16;
  const int wn = (warp & 1) * 32;
  const int ldr = tid >> 3;          // 0..31
  const int c8 = (tid & 7) * 8;

  // load Q (64x64 bf16)
#pragma unroll
  for (int r = 0; r < 2; r++) {
    const int row = ldr + r * 32;
    *(float4*)&Qs[row * FTS2 + c8] =
        *(const float4*)&Q[((size_t)hh * CT + qb * 64 + row) * 64 + c8];
  }
  if (tid < 64) { mrow[tid] = -1e30f; lrow[tid] = 0.f; }

  float oacc[4][4];
#pragma unroll
  for (int i = 0; i < 4; i++)
#pragma unroll
    for (int j = 0; j < 4; j++) oacc[i][j] = 0.f;

  const int arow_ = wm + (lane & 15);
  const int acol = (lane >> 4) * 8;
  const int g8 = lane >> 3;
  const int brow = wn + (g8 >> 1) * 8 + (lane & 7);
  const int bcol = (g8 & 1) * 8;

  for (int kb = 0; kb <= qb; kb++) {
    __syncthreads();
    // load K rows + V transposed
#pragma unroll
    for (int r = 0; r < 2; r++) {
      const int row = ldr + r * 32;
      const size_t gbase = ((size_t)hk * CT + kb * 64 + row) * 64 + c8;
      *(float4*)&Ks[row * FTS2 + c8] = *(const float4*)&Kg[gbase];
      const uint4 vv = *(const uint4*)&Vg[gbase];
      const bf16* pv = (const bf16*)&vv;
#pragma unroll
      for (int j = 0; j < 8; j++) Vt[(c8 + j) * FTS2 + row] = pv[j];
    }
    __syncthreads();

    // S = Q K^T
    float sacc[4][4];
#pragma unroll
    for (int i = 0; i < 4; i++)
#pragma unroll
      for (int j = 0; j < 4; j++) sacc[i][j] = 0.f;
#pragma unroll
    for (int ks = 0; ks < 4; ks++) {
      uint32_t a[4], b[2][4];
      ldm4(a, &Qs[arow_ * FTS2 + ks * 16 + acol]);
      ldm4(b[0], &Ks[brow * FTS2 + ks * 16 + bcol]);
      ldm4(b[1], &Ks[(brow + 16) * FTS2 + ks * 16 + bcol]);
#pragma unroll
      for (int fn = 0; fn < 4; fn++)
        mma_bf16(sacc[fn], a, &b[fn >> 1][(fn & 1) * 2]);
    }

    // scale + causal mask + row max
    const bool diag = (kb == qb);
    float rmax0 = -1e30f, rmax1 = -1e30f;
#pragma unroll
    for (int fn = 0; fn < 4; fn++) {
      const int c = wn + fn * 8 + 2 * ti;
#pragma unroll
      for (int l = 0; l < 4; l++) {
        float v = sacc[fn][l] * 0.125f;
        const int row = wm + gi + ((l >= 2) ? 8 : 0);
        const int col = c + (l & 1);
        if (diag && col > row) v = -1e30f;
        sacc[fn][l] = v;
        if (l >= 2) rmax1 = fmaxf(rmax1, v);
        else rmax0 = fmaxf(rmax0, v);
      }
    }
    rmax0 = fmaxf(rmax0, __shfl_xor_sync(0xffffffffu, rmax0, 1));
    rmax0 = fmaxf(rmax0, __shfl_xor_sync(0xffffffffu, rmax0, 2));
    rmax1 = fmaxf(rmax1, __shfl_xor_sync(0xffffffffu, rmax1, 1));
    rmax1 = fmaxf(rmax1, __shfl_xor_sync(0xffffffffu, rmax1, 2));
    if (ti == 0) {
      redm[(wm + gi) * 2 + (warp & 1)] = rmax0;
      redm[(wm + gi + 8) * 2 + (warp & 1)] = rmax1;
    }
    __syncthreads();
    if (tid < 64) {
      const float mold = mrow[tid];
      const float mnew = fmaxf(mold, fmaxf(redm[tid * 2], redm[tid * 2 + 1]));
      const float al = __expf(mold - mnew);
      mrow[tid] = mnew; arow[tid] = al; lrow[tid] *= al;
    }
    __syncthreads();

    const float m0 = mrow[wm + gi], m1 = mrow[wm + gi + 8];
    const float a0 = arow[wm + gi], a1 = arow[wm + gi + 8];
    float rs0 = 0.f, rs1 = 0.f;
#pragma unroll
    for (int fn = 0; fn < 4; fn++) {
      const int c = wn + fn * 8 + 2 * ti;
      const float p00 = __expf(sacc[fn][0] - m0);
      const float p01 = __expf(sacc[fn][1] - m0);
      const float p10 = __expf(sacc[fn][2] - m1);
      const float p11 = __expf(sacc[fn][3] - m1);
      rs0 += p00 + p01; rs1 += p10 + p11;
      *(bf162*)&Ps[(wm + gi) * FTS2 + c] = __floats2bfloat162_rn(p00, p01);
      *(bf162*)&Ps[(wm + gi + 8) * FTS2 + c] = __floats2bfloat162_rn(p10, p11);
    }
    rs0 += __shfl_xor_sync(0xffffffffu, rs0, 1);
    rs0 += __shfl_xor_sync(0xffffffffu, rs0, 2);
    rs1 += __shfl_xor_sync(0xffffffffu, rs1, 1);
    rs1 += __shfl_xor_sync(0xffffffffu, rs1, 2);
    if (ti == 0) {
      redl[(wm + gi) * 2 + (warp & 1)] = rs0;
      redl[(wm + gi + 8) * 2 + (warp & 1)] = rs1;
    }
    // rescale accumulators
#pragma unroll
    for (int fn = 0; fn < 4; fn++) {
      oacc[fn][0] *= a0; oacc[fn][1] *= a0;
      oacc[fn][2] *= a1; oacc[fn][3] *= a1;
    }
    __syncthreads();
    if (tid < 64) lrow[tid] += redl[tid * 2] + redl[tid * 2 + 1];

    // O += P V  (A = Ps rows, B = Vt rows (n = d))
#pragma unroll
    for (int ks = 0; ks < 4; ks++) {
      uint32_t a[4], b[2][4];
      ldm4(a, &Ps[arow_ * FTS2 + ks * 16 + acol]);
      ldm4(b[0], &Vt[brow * FTS2 + ks * 16 + bcol]);
      ldm4(b[1], &Vt[(brow + 16) * FTS2 + ks * 16 + bcol]);
#pragma unroll
      for (int fn = 0; fn < 4; fn++)
        mma_bf16(oacc[fn], a, &b[fn >> 1][(fn & 1) * 2]);
    }
  }
  __syncthreads();

  const float inv0 = 1.f / lrow[wm + gi];
  const float inv1 = 1.f / lrow[wm + gi + 8];
#pragma unroll
  for (int fn = 0; fn < 4; fn++) {
    const int col = hh * 64 + wn + fn * 8 + 2 * ti;
    *(bf162*)&Og[(size_t)(qb * 64 + wm + gi) * CD + col] =
        __floats2bfloat162_rn(oacc[fn][0] * inv0, oacc[fn][1] * inv0);
    *(bf162*)&Og[(size_t)(qb * 64 + wm + gi + 8) * CD + col] =
        __floats2bfloat162_rn(oacc[fn][2] * inv1, oacc[fn][3] * inv1);
  }
}

// ---------------------------------------------------------------------------
// act = silu(gate) * up
// ---------------------------------------------------------------------------
__global__ void silu_mul_bf(bf16* __restrict__ gate,
                            const bf16* __restrict__ up) {
  const size_t i = ((size_t)blockIdx.x * 256 + threadIdx.x) * 4;
  bf162 g0 = *(bf162*)&gate[i];
  bf162 g1 = *(bf162*)&gate[i + 2];
  const bf162 u0 = *(const bf162*)&up[i];
  const bf162 u1 = *(const bf162*)&up[i + 2];
  float a = __bfloat162float(g0.x), b = __bfloat162float(g0.y);
  float c = __bfloat162float(g1.x), d = __bfloat162float(g1.y);
  a = a / (1.f + __expf(-a)) * __bfloat162float(u0.x);
  b = b / (1.f + __expf(-b)) * __bfloat162float(u0.y);
  c = c / (1.f + __expf(-c)) * __bfloat162float(u1.x);
  d = d / (1.f + __expf(-d)) * __bfloat162float(u1.y);
  *(bf162*)&gate[i] = __floats2bfloat162_rn(a, b);
  *(bf162*)&gate[i + 2] = __floats2bfloat162_rn(c, d);
}

// ---------------------------------------------------------------------------
// Launch pipeline
// ---------------------------------------------------------------------------
extern "C" void kernel_launch(void* const* d_in, const int* in_sizes, int n_in,
                              void* d_out, int out_size) {
  const float* hidden = (const float*)d_in[0];
  const float* ln1 = (const float*)d_in[1];
  const float* ln2 = (const float*)d_in[2];
  const float* q_Us = (const float*)d_in[3];
  const float* q_V  = (const float*)d_in[4];
  const float* k_Us = (const float*)d_in[5];
  const float* k_V  = (const float*)d_in[6];
  const float* v_Us = (const float*)d_in[7];
  const float* v_V  = (const float*)d_in[8];
  const float* o_Us = (const float*)d_in[9];
  const float* o_V  = (const float*)d_in[10];
  const float* g_Us = (const float*)d_in[11];
  const float* g_V  = (const float*)d_in[12];
  const float* u_Us = (const float*)d_in[13];
  const float* u_V  = (const float*)d_in[14];
  const float* d_Us = (const float*)d_in[15];
  const float* d_V  = (const float*)d_in[16];
  float* out = (float*)d_out;

  Scratch* s = nullptr;
  cudaGetSymbolAddress((void**)&s, g_scratch);

  cudaFuncSetAttribute(flash_attn_bf,
                       cudaFuncAttributeMaxDynamicSharedMemorySize,
                       FA_SMEM_BYTES);

  // 0. convert weights to bf16 (qV|kV|vV pack contiguously)
  {
    CvtPack p;
    const float* srcs[NCVT] = {q_V, k_V, v_V, o_Us, o_V, g_Us,
                               g_V, u_Us, u_V, d_Us, d_V};
    bf16* dsts[NCVT] = {s->qV, s->kV, s->vV, s->oUs, s->oV, s->gUs,
                        s->gV, s->uUs, s->uV, s->dUs, s->dV};
    const int ns[NCVT] = {1024 * CD, 256 * CD, 256 * CD, CD * 512, 512 * CD,
                          CINTER * 512, 512 * CD, CINTER * 512, 512 * CD,
                          CD * 512, 512 * CINTER};
    int total4 = 0;
    for (int i = 0; i < NCVT; i++) {
      p.src[i] = srcs[i]; p.dst[i] = dsts[i]; p.n4[i] = ns[i] / 4;
      total4 += ns[i] / 4;
    }
    cvt_f2bf<<<(total4 + 255) / 256, 256>>>(p, total4);
  }

  // 1. x = rmsnorm(hidden, ln1) -> bf16
  rmsnorm_bf<<<CT, 256>>>(hidden, ln1, s->x);

  // 2. fused QKV low-rank projection: x * [qV;kV;vV]^T -> Pqkv (fp32)
  gemm_bf<false><<<dim3(12, 16, 1), 256>>>(s->x, s->qV, nullptr, s->Pqkv,
                                           nullptr, nullptr, nullptr, nullptr,
                                           1536, CD);

  // 3. Us up-projections + RoPE -> bf16 q/k/v
  proj_us_rope<<<dim3(CT / 32, CH), dim3(32, 8)>>>(s->Pqkv, q_Us, s->q,
                                                   1536, 1);
  proj_us_rope<<<dim3(CT / 32, CHK), dim3(32, 8)>>>(s->Pqkv + 1024, k_Us,
                                                    s->k, 1536, 1);
  proj_us_rope<<<dim3(CT / 32, CHK), dim3(32, 8)>>>(s->Pqkv + 1280, v_Us,
                                                    s->v, 1536, 0);

  // 4. attention -> bf16
  flash_attn_bf<<<dim3(CT / 64, CH), 256, FA_SMEM_BYTES>>>(s->q, s->k, s->v,
                                                           s->attn);

  // 5. output projection (split-K=2) + residual -> h
  gemm_bf_sk<<<dim3(4, 16, 2), 256>>>(s->attn, s->oV, s->skpart, 512, CD,
                                      1024);
  reduce_sk<<<CT * 512 / 1024, 256>>>(s->skpart, s->Po, CT * 512, 2);
  gemm_bf<false><<<dim3(16, 16, 1), 256>>>(s->Po, s->oUs, hidden, s->h,
                                           nullptr, nullptr, nullptr, nullptr,
                                           CD, 512);

  // 6. FFN
  rmsnorm_bf<<<CT, 256>>>(s->h, ln2, s->x);
  gemm_bf<true><<<dim3(4, 16, 2), 256>>>(s->x, s->gV, nullptr, s->Pg,
                                         s->x, s->uV, nullptr, s->Pu,
                                         512, CD);
  gemm_bf<true><<<dim3(64, 16, 2), 256>>>(s->Pg, s->gUs, nullptr, s->gate,
                                          s->Pu, s->uUs, nullptr, s->up,
                                          CINTER, 512);
  silu_mul_bf<<<(CT * CINTER / 4) / 256, 256>>>(s->gate, s->up);
  gemm_bf_sk<<<dim3(4, 16, 4), 256>>>(s->gate, s->dV, s->skpart, 512, CINTER,
                                      2048);
  reduce_sk<<<CT * 512 / 1024, 256>>>(s->skpart, s->Pd, CT * 512, 4);
  gemm_bf<false><<<dim3(16, 16, 1), 256>>>(s->Pd, s->dUs, s->h, out,
                                           nullptr, nullptr, nullptr, nullptr,
                                           CD, 512);
}

// round 6
// speedup vs baseline: 7.6801x; 1.0808x over previous
#include <cuda_runtime.h>
#include <cuda_bf16.h>
#include <math.h>
#include <cstdint>

#define CT 2048
#define CD 2048
#define CH 32
#define CHK 8
#define CDH 64
#define CINTER 8192

typedef __nv_bfloat16 bf16;
typedef __nv_bfloat162 bf162;

// ---------------------------------------------------------------------------
// Static device scratch
// ---------------------------------------------------------------------------
struct alignas(256) Scratch {
  float Pqkv[CT * 1536];
  float h[CT * CD];
  float skpart[4 * CT * 512];
  float ropeC[CT * 32];
  float ropeS[CT * 32];
  bf16 x[CT * CD];
  bf16 q[CH * CT * CDH];
  bf16 k[CHK * CT * CDH];
  bf16 v[CHK * CT * CDH];
  bf16 attn[CT * CD];
  bf16 Po[CT * 512];
  bf16 Pg[CT * 512];
  bf16 Pu[CT * 512];
  bf16 gate[CT * CINTER];
  bf16 up[CT * CINTER];
  bf16 Pd[CT * 512];
  bf16 qV[1024 * CD];
  bf16 kV[256 * CD];
  bf16 vV[256 * CD];
  bf16 oUs[CD * 512];
  bf16 oV[512 * CD];
  bf16 gUs[CINTER * 512];
  bf16 gV[512 * CD];
  bf16 uUs[CINTER * 512];
  bf16 uV[512 * CD];
  bf16 dUs[CD * 512];
  bf16 dV[512 * CINTER];
};
__device__ Scratch g_scratch;

// ---------------------------------------------------------------------------
// helpers
// ---------------------------------------------------------------------------
__device__ __forceinline__ void cp16(void* s, const void* g) {
  uint32_t sa = (uint32_t)__cvta_generic_to_shared(s);
  asm volatile("cp.async.cg.shared.global [%0], [%1], 16;" ::"r"(sa), "l"(g));
}
__device__ __forceinline__ void mma_bf16(float* c, const uint32_t* a,
                                         const uint32_t* b) {
  asm volatile(
      "mma.sync.aligned.m16n8k16.row.col.f32.bf16.bf16.f32 "
      "{%0,%1,%2,%3}, {%4,%5,%6,%7}, {%8,%9}, {%0,%1,%2,%3};"
      : "+f"(c[0]), "+f"(c[1]), "+f"(c[2]), "+f"(c[3])
      : "r"(a[0]), "r"(a[1]), "r"(a[2]), "r"(a[3]), "r"(b[0]), "r"(b[1]));
}
__device__ __forceinline__ void ldm4(uint32_t* r, const void* p) {
  uint32_t a = (uint32_t)__cvta_generic_to_shared(p);
  asm volatile(
      "ldmatrix.sync.aligned.m8n8.x4.shared.b16 {%0,%1,%2,%3}, [%4];"
      : "=r"(r[0]), "=r"(r[1]), "=r"(r[2]), "=r"(r[3])
      : "r"(a));
}
__device__ __forceinline__ uint32_t packbf(float a, float b) {
  bf162 v = __floats2bfloat162_rn(a, b);
  return *(uint32_t*)&v;
}

// ---------------------------------------------------------------------------
// weight conversion fp32 -> bf16
// ---------------------------------------------------------------------------
#define NCVT 11
struct CvtPack {
  const float* src[NCVT];
  bf16* dst[NCVT];
  int n4[NCVT];
};
__global__ void cvt_f2bf(CvtPack p, int total4) {
  int i = blockIdx.x * 256 + threadIdx.x;
  if (i >= total4) return;
  int s = 0, off = i;
  while (off >= p.n4[s]) { off -= p.n4[s]; s++; }
  const float4 v = ((const float4*)p.src[s])[off];
  bf162* d = (bf162*)p.dst[s];
  d[off * 2] = __floats2bfloat162_rn(v.x, v.y);
  d[off * 2 + 1] = __floats2bfloat162_rn(v.z, v.w);
}

// rope cos/sin table
__global__ void rope_tab(float* __restrict__ c, float* __restrict__ s) {
  const int i = blockIdx.x * 256 + threadIdx.x;
  const int t = i >> 5, d = i & 31;
  const float invf = exp2f(-0.41524101186092028f * (float)d);
  float sn, cs;
  sincosf((float)t * invf, &sn, &cs);
  c[i] = cs;
  s[i] = sn;
}

// ---------------------------------------------------------------------------
// RMSNorm (fp32 in, bf16 out)
// ---------------------------------------------------------------------------
__global__ void rmsnorm_bf(const float* __restrict__ in,
                           const float* __restrict__ w,
                           bf16* __restrict__ out) {
  const int t = blockIdx.x;
  const float* row = in + (size_t)t * CD;
  float ss = 0.f;
  for (int i = threadIdx.x; i < CD; i += 256) {
    float v = row[i];
    ss += v * v;
  }
  __shared__ float red[8];
#pragma unroll
  for (int o = 16; o > 0; o >>= 1) ss += __shfl_xor_sync(0xffffffffu, ss, o);
  if ((threadIdx.x & 31) == 0) red[threadIdx.x >> 5] = ss;
  __syncthreads();
  if (threadIdx.x == 0) {
    float v = 0.f;
#pragma unroll
    for (int i = 0; i < 8; i++) v += red[i];
    red[0] = v;
  }
  __syncthreads();
  const float inv = rsqrtf(red[0] * (1.0f / CD) + 1e-5f);
  for (int i = threadIdx.x * 2; i < CD; i += 512) {
    bf162 o = __floats2bfloat162_rn(row[i] * inv * w[i],
                                    row[i + 1] * inv * w[i + 1]);
    *(bf162*)&out[(size_t)t * CD + i] = o;
  }
}

// ---------------------------------------------------------------------------
// bf16 tensor-core GEMM (NT): C = A * B^T. 128x128x32 tiles.
// MODE 0: fp32 out (+res). 1: bf16 out. 2: bf16 silu(out). 3: bf16 out*aux.
// ---------------------------------------------------------------------------
template <int MODE>
__global__ __launch_bounds__(256, 2) void gemm_bf(
    const bf16* __restrict__ A1, const bf16* __restrict__ B1,
    const float* __restrict__ res1, void* __restrict__ C1,
    const bf16* __restrict__ A2, const bf16* __restrict__ B2,
    const float* __restrict__ res2, void* __restrict__ C2,
    const bf16* __restrict__ aux, int N, int K) {
  const bf16* A = blockIdx.z ? A2 : A1;
  const bf16* B = blockIdx.z ? B2 : B1;
  const float* res = blockIdx.z ? res2 : res1;
  void* C = blockIdx.z ? C2 : C1;

  __shared__ bf16 As[2][128][40];
  __shared__ bf16 Bs[2][128][40];

  const int tid = threadIdx.x;
  const int lane = tid & 31, warp = tid >> 5;
  const int wm = (warp & 1) * 64, wn = (warp >> 1) * 32;
  const int bm = blockIdx.y * 128, bn = blockIdx.x * 128;
  const int gi = lane >> 2, ti = lane & 3;
  const int grow = tid >> 1;
  const int gcol = (tid & 1) * 16;

  float acc[4][4][4];
#pragma unroll
  for (int i = 0; i < 4; i++)
#pragma unroll
    for (int j = 0; j < 4; j++)
#pragma unroll
      for (int l = 0; l < 4; l++) acc[i][j][l] = 0.f;

  const int nt = K >> 5;
  {
    const bf16* ga = &A[(size_t)(bm + grow) * K + gcol];
    cp16(&As[0][grow][gcol], ga);
    cp16(&As[0][grow][gcol + 8], ga + 8);
    const bf16* gb = &B[(size_t)(bn + grow) * K + gcol];
    cp16(&Bs[0][grow][gcol], gb);
    cp16(&Bs[0][grow][gcol + 8], gb + 8);
    asm volatile("cp.async.commit_group;" ::: "memory");
  }

  const int arow = wm + (lane & 15);
  const int acol = (lane >> 4) * 8;
  const int g8 = lane >> 3;
  const int brow = wn + (g8 >> 1) * 8 + (lane & 7);
  const int bcol = (g8 & 1) * 8;

  for (int t = 0; t < nt; t++) {
    const int buf = t & 1;
    if (t + 1 < nt) {
      const int k0 = (t + 1) << 5;
      const bf16* ga = &A[(size_t)(bm + grow) * K + k0 + gcol];
      cp16(&As[buf ^ 1][grow][gcol], ga);
      cp16(&As[buf ^ 1][grow][gcol + 8], ga + 8);
      const bf16* gb = &B[(size_t)(bn + grow) * K + k0 + gcol];
      cp16(&Bs[buf ^ 1][grow][gcol], gb);
      cp16(&Bs[buf ^ 1][grow][gcol + 8], gb + 8);
      asm volatile("cp.async.commit_group;" ::: "memory");
      asm volatile("cp.async.wait_group 1;" ::: "memory");
    } else {
      asm volatile("cp.async.wait_group 0;" ::: "memory");
    }
    __syncthreads();

#pragma unroll
    for (int ks = 0; ks < 2; ks++) {
      uint32_t a[4][4], b[2][4];
#pragma unroll
      for (int fm = 0; fm < 4; fm++)
        ldm4(a[fm], &As[buf][arow + fm * 16][ks * 16 + acol]);
      ldm4(b[0], &Bs[buf][brow][ks * 16 + bcol]);
      ldm4(b[1], &Bs[buf][brow + 16][ks * 16 + bcol]);
#pragma unroll
      for (int fm = 0; fm < 4; fm++)
#pragma unroll
        for (int fn = 0; fn < 4; fn++)
          mma_bf16(acc[fm][fn], a[fm], &b[fn >> 1][(fn & 1) * 2]);
    }
    __syncthreads();
  }

#pragma unroll
  for (int fm = 0; fm < 4; fm++) {
#pragma unroll
    for (int fn = 0; fn < 4; fn++) {
      const int r = bm + wm + fm * 16 + gi;
      const int c = bn + wn + fn * 8 + ti * 2;
      float v[4] = {acc[fm][fn][0], acc[fm][fn][1], acc[fm][fn][2],
                    acc[fm][fn][3]};
      if (MODE == 0) {
        float* Cf = (float*)C;
        if (res) {
          const float2 r0 = *(const float2*)&res[(size_t)r * N + c];
          const float2 r1 = *(const float2*)&res[(size_t)(r + 8) * N + c];
          v[0] += r0.x; v[1] += r0.y; v[2] += r1.x; v[3] += r1.y;
        }
        *(float2*)&Cf[(size_t)r * N + c] = make_float2(v[0], v[1]);
        *(float2*)&Cf[(size_t)(r + 8) * N + c] = make_float2(v[2], v[3]);
      } else {
        if (MODE == 2) {
#pragma unroll
          for (int l = 0; l < 4; l++) v[l] = v[l] / (1.f + __expf(-v[l]));
        }
        if (MODE == 3) {
          const bf162 a0 = *(const bf162*)&aux[(size_t)r * N + c];
          const bf162 a1 = *(const bf162*)&aux[(size_t)(r + 8) * N + c];
          v[0] *= __bfloat162float(a0.x); v[1] *= __bfloat162float(a0.y);
          v[2] *= __bfloat162float(a1.x); v[3] *= __bfloat162float(a1.y);
        }
        bf16* Cb = (bf16*)C;
        *(bf162*)&Cb[(size_t)r * N + c] = __floats2bfloat162_rn(v[0], v[1]);
        *(bf162*)&Cb[(size_t)(r + 8) * N + c] =
            __floats2bfloat162_rn(v[2], v[3]);
      }
    }
  }
}

// ---------------------------------------------------------------------------
// split-K bf16 GEMM + reducer
// ---------------------------------------------------------------------------
__global__ __launch_bounds__(256, 2) void gemm_bf_sk(
    const bf16* __restrict__ A, const bf16* __restrict__ B,
    float* __restrict__ Cpart, int N, int K, int Kc) {
  __shared__ bf16 As[2][128][40];
  __shared__ bf16 Bs[2][128][40];

  const int tid = threadIdx.x;
  const int lane = tid & 31, warp = tid >> 5;
  const int wm = (warp & 1) * 64, wn = (warp >> 1) * 32;
  const int bm = blockIdx.y * 128, bn = blockIdx.x * 128;
  const int gi = lane >> 2, ti = lane & 3;
  const int grow = tid >> 1;
  const int gcol = (tid & 1) * 16;
  const int kbase = blockIdx.z * Kc;
  float* C = Cpart + (size_t)blockIdx.z * CT * N;

  float acc[4][4][4];
#pragma unroll
  for (int i = 0; i < 4; i++)
#pragma unroll
    for (int j = 0; j < 4; j++)
#pragma unroll
      for (int l = 0; l < 4; l++) acc[i][j][l] = 0.f;

  const int nt = Kc >> 5;
  {
    const bf16* ga = &A[(size_t)(bm + grow) * K + kbase + gcol];
    cp16(&As[0][grow][gcol], ga);
    cp16(&As[0][grow][gcol + 8], ga + 8);
    const bf16* gb = &B[(size_t)(bn + grow) * K + kbase + gcol];
    cp16(&Bs[0][grow][gcol], gb);
    cp16(&Bs[0][grow][gcol + 8], gb + 8);
    asm volatile("cp.async.commit_group;" ::: "memory");
  }

  const int arow = wm + (lane & 15);
  const int acol = (lane >> 4) * 8;
  const int g8 = lane >> 3;
  const int brow = wn + (g8 >> 1) * 8 + (lane & 7);
  const int bcol = (g8 & 1) * 8;

  for (int t = 0; t < nt; t++) {
    const int buf = t & 1;
    if (t + 1 < nt) {
      const int k0 = kbase + ((t + 1) << 5);
      const bf16* ga = &A[(size_t)(bm + grow) * K + k0 + gcol];
      cp16(&As[buf ^ 1][grow][gcol], ga);
      cp16(&As[buf ^ 1][grow][gcol + 8], ga + 8);
      const bf16* gb = &B[(size_t)(bn + grow) * K + k0 + gcol];
      cp16(&Bs[buf ^ 1][grow][gcol], gb);
      cp16(&Bs[buf ^ 1][grow][gcol + 8], gb + 8);
      asm volatile("cp.async.commit_group;" ::: "memory");
      asm volatile("cp.async.wait_group 1;" ::: "memory");
    } else {
      asm volatile("cp.async.wait_group 0;" ::: "memory");
    }
    __syncthreads();

#pragma unroll
    for (int ks = 0; ks < 2; ks++) {
      uint32_t a[4][4], b[2][4];
#pragma unroll
      for (int fm = 0; fm < 4; fm++)
        ldm4(a[fm], &As[buf][arow + fm * 16][ks * 16 + acol]);
      ldm4(b[0], &Bs[buf][brow][ks * 16 + bcol]);
      ldm4(b[1], &Bs[buf][brow + 16][ks * 16 + bcol]);
#pragma unroll
      for (int fm = 0; fm < 4; fm++)
#pragma unroll
        for (int fn = 0; fn < 4; fn++)
          mma_bf16(acc[fm][fn], a[fm], &b[fn >> 1][(fn & 1) * 2]);
    }
    __syncthreads();
  }

#pragma unroll
  for (int fm = 0; fm < 4; fm++) {
#pragma unroll
    for (int fn = 0; fn < 4; fn++) {
      const int r = bm + wm + fm * 16 + gi;
      const int c = bn + wn + fn * 8 + ti * 2;
      *(float2*)&C[(size_t)r * N + c] =
          make_float2(acc[fm][fn][0], acc[fm][fn][1]);
      *(float2*)&C[(size_t)(r + 8) * N + c] =
          make_float2(acc[fm][fn][2], acc[fm][fn][3]);
    }
  }
}

__global__ void reduce_sk(const float* __restrict__ part,
                          bf16* __restrict__ out, int MN, int S) {
  const int i = (blockIdx.x * 256 + threadIdx.x) * 4;
  if (i >= MN) return;
  float4 a = *(const float4*)&part[i];
  for (int s = 1; s < S; s++) {
    const float4 p = *(const float4*)&part[(size_t)s * MN + i];
    a.x += p.x; a.y += p.y; a.z += p.z; a.w += p.w;
  }
  *(bf162*)&out[i] = __floats2bfloat162_rn(a.x, a.y);
  *(bf162*)&out[i + 2] = __floats2bfloat162_rn(a.z, a.w);
}

// ---------------------------------------------------------------------------
// Per-head Us projection + optional RoPE (from table). fp32 in, bf16 out.
// ---------------------------------------------------------------------------
__global__ void proj_us_rope(const float* __restrict__ P,
                             const float* __restrict__ Us,
                             const float* __restrict__ tC,
                             const float* __restrict__ tS,
                             bf16* __restrict__ out, int pstride, int doRope) {
  const int hh = blockIdx.y;
  const int tg = threadIdx.y;
  const int dh = threadIdx.x;
  const int t0 = blockIdx.x * 32 + tg * 4;
  __shared__ float sUs[64][33];
  __shared__ float sP[32][33];
  const int tid = tg * 32 + dh;
  const float* UsH = Us + (size_t)hh * 64 * 32;
#pragma unroll
  for (int i = tid; i < 64 * 32; i += 256) sUs[i >> 5][i & 31] = UsH[i];
#pragma unroll
  for (int j = 0; j < 4; j++)
    sP[tg * 4 + j][dh] = P[(size_t)(t0 + j) * pstride + hh * 32 + dh];
  __syncthreads();
  float x1[4] = {0.f, 0.f, 0.f, 0.f}, x2[4] = {0.f, 0.f, 0.f, 0.f};
#pragma unroll
  for (int r = 0; r < 32; r++) {
    const float u1 = sUs[dh][r];
    const float u2 = sUs[dh + 32][r];
#pragma unroll
    for (int j = 0; j < 4; j++) {
      const float p = sP[tg * 4 + j][r];
      x1[j] = fmaf(p, u1, x1[j]);
      x2[j] = fmaf(p, u2, x2[j]);
    }
  }
#pragma unroll
  for (int j = 0; j < 4; j++) {
    float o1 = x1[j], o2 = x2[j];
    if (doRope) {
      const float cs = tC[(t0 + j) * 32 + dh];
      const float sn = tS[(t0 + j) * 32 + dh];
      o1 = x1[j] * cs - x2[j] * sn;
      o2 = x2[j] * cs + x1[j] * sn;
    }
    const size_t base = ((size_t)hh * CT + t0 + j) * CDH;
    out[base + dh] = __float2bfloat16(o1);
    out[base + dh + 32] = __float2bfloat16(o2);
  }
}

// ---------------------------------------------------------------------------
// bf16 causal flash attention, FA2-style. Q tile 128 rows, 8 warps x 16 rows.
// All softmax stats warp-local; P stays in registers.
// ---------------------------------------------------------------------------
#define FTS2 72
__global__ __launch_bounds__(256) void flash_attn_bf(
    const bf16* __restrict__ Q, const bf16* __restrict__ Kg,
    const bf16* __restrict__ Vg, bf16* __restrict__ Og) {
  __shared__ bf16 Qs[128 * FTS2];
  __shared__ bf16 Ks[64 * FTS2];
  __shared__ bf16 Vt[64 * FTS2];

  const int qb = blockIdx.x, hh = blockIdx.y, hk = hh >> 2;
  const int tid = threadIdx.x;
  const int lane = tid & 31, warp = tid >> 5;
  const int gi = lane >> 2, ti = lane & 3;
  const int wm = warp * 16;  // warp's 16 rows within the 128-row tile
  const int ldr = tid >> 3, c8 = (tid & 7) * 8;

  // load Q (128x64)
#pragma unroll
  for (int r = 0; r < 4; r++) {
    const int row = ldr + r * 32;
    *(float4*)&Qs[row * FTS2 + c8] =
        *(const float4*)&Q[((size_t)hh * CT + qb * 128 + row) * 64 + c8];
  }
  __syncthreads();

  // Q fragments -> registers (held whole kernel)
  const int arow_ = wm + (lane & 15);
  const int acol = (lane >> 4) * 8;
  uint32_t aq[4][4];
#pragma unroll
  for (int ks = 0; ks < 4; ks++)
    ldm4(aq[ks], &Qs[arow_ * FTS2 + ks * 16 + acol]);

  const int g8 = lane >> 3;
  const int nbrow = (g8 >> 1) * 8 + (lane & 7);
  const int bcol = (g8 & 1) * 8;

  float m0 = -1e30f, m1 = -1e30f, l0 = 0.f, l1 = 0.f;
  float oacc[8][4];
#pragma unroll
  for (int i = 0; i < 8; i++)
#pragma unroll
    for (int j = 0; j < 4; j++) oacc[i][j] = 0.f;

  const int row0 = qb * 128 + wm + gi;
  const int kbmax = 2 * qb + 1;

  for (int kb = 0; kb <= kbmax; kb++) {
    __syncthreads();
#pragma unroll
    for (int r = 0; r < 2; r++) {
      const int row = ldr + r * 32;
      const size_t gbase = ((size_t)hk * CT + kb * 64 + row) * 64 + c8;
      *(float4*)&Ks[row * FTS2 + c8] = *(const float4*)&Kg[gbase];
      const uint4 vv = *(const uint4*)&Vg[gbase];
      const bf16* pv = (const bf16*)&vv;
#pragma unroll
      for (int j = 0; j < 8; j++) Vt[(c8 + j) * FTS2 + row] = pv[j];
    }
    __syncthreads();

    // S = Q K^T   (8 n-blocks of 8)
    float sacc[8][4];
#pragma unroll
    for (int i = 0; i < 8; i++)
#pragma unroll
      for (int j = 0; j < 4; j++) sacc[i][j] = 0.f;
#pragma unroll
    for (int ks = 0; ks < 4; ks++) {
      uint32_t b[4][4];
#pragma unroll
      for (int nb = 0; nb < 4; nb++)
        ldm4(b[nb], &Ks[(nbrow + nb * 16) * FTS2 + ks * 16 + bcol]);
#pragma unroll
      for (int fn = 0; fn < 8; fn++)
        mma_bf16(sacc[fn], aq[ks], &b[fn >> 1][(fn & 1) * 2]);
    }

    // scale + mask + warp-local softmax
    const bool needMask = (kb * 64 + 63) > row0;
    float rmax0 = -1e30f, rmax1 = -1e30f;
#pragma unroll
    for (int fn = 0; fn < 8; fn++) {
      const int c = kb * 64 + fn * 8 + 2 * ti;
#pragma unroll
      for (int l = 0; l < 4; l++) {
        float v = sacc[fn][l] * 0.125f;
        if (needMask) {
          const int row = row0 + ((l >= 2) ? 8 : 0);
          if (c + (l & 1) > row) v = -1e30f;
        }
        sacc[fn][l] = v;
        if (l >= 2) rmax1 = fmaxf(rmax1, v);
        else rmax0 = fmaxf(rmax0, v);
      }
    }
    rmax0 = fmaxf(rmax0, __shfl_xor_sync(0xffffffffu, rmax0, 1));
    rmax0 = fmaxf(rmax0, __shfl_xor_sync(0xffffffffu, rmax0, 2));
    rmax1 = fmaxf(rmax1, __shfl_xor_sync(0xffffffffu, rmax1, 1));
    rmax1 = fmaxf(rmax1, __shfl_xor_sync(0xffffffffu, rmax1, 2));
    const float mn0 = fmaxf(m0, rmax0), mn1 = fmaxf(m1, rmax1);
    const float al0 = __expf(m0 - mn0), al1 = __expf(m1 - mn1);
    m0 = mn0; m1 = mn1;

    float rs0 = 0.f, rs1 = 0.f;
    uint32_t ap[4][4];
#pragma unroll
    for (int ks = 0; ks < 4; ks++) {
      const int f0 = 2 * ks, f1 = 2 * ks + 1;
      const float p00 = __expf(sacc[f0][0] - m0);
      const float p01 = __expf(sacc[f0][1] - m0);
      const float p02 = __expf(sacc[f0][2] - m1);
      const float p03 = __expf(sacc[f0][3] - m1);
      const float p10 = __expf(sacc[f1][0] - m0);
      const float p11 = __expf(sacc[f1][1] - m0);
      const float p12 = __expf(sacc[f1][2] - m1);
      const float p13 = __expf(sacc[f1][3] - m1);
      rs0 += p00 + p01 + p10 + p11;
      rs1 += p02 + p03 + p12 + p13;
      ap[ks][0] = packbf(p00, p01);
      ap[ks][1] = packbf(p02, p03);
      ap[ks][2] = packbf(p10, p11);
      ap[ks][3] = packbf(p12, p13);
    }
    rs0 += __shfl_xor_sync(0xffffffffu, rs0, 1);
    rs0 += __shfl_xor_sync(0xffffffffu, rs0, 2);
    rs1 += __shfl_xor_sync(0xffffffffu, rs1, 1);
    rs1 += __shfl_xor_sync(0xffffffffu, rs1, 2);
    l0 = l0 * al0 + rs0;
    l1 = l1 * al1 + rs1;
#pragma unroll
    for (int fn = 0; fn < 8; fn++) {
      oacc[fn][0] *= al0; oacc[fn][1] *= al0;
      oacc[fn][2] *= al1; oacc[fn][3] *= al1;
    }

    // O += P V
#pragma unroll
    for (int ks = 0; ks < 4; ks++) {
      uint32_t b[4][4];
#pragma unroll
      for (int nb = 0; nb < 4; nb++)
        ldm4(b[nb], &Vt[(nbrow + nb * 16) * FTS2 + ks * 16 + bcol]);
#pragma unroll
      for (int fn = 0; fn < 8; fn++)
        mma_bf16(oacc[fn], ap[ks], &b[fn >> 1][(fn & 1) * 2]);
    }
  }

  const float inv0 = 1.f / l0, inv1 = 1.f / l1;
#pragma unroll
  for (int fn = 0; fn < 8; fn++) {
    const int col = hh * 64 + fn * 8 + 2 * ti;
    *(bf162*)&Og[(size_t)(row0) * CD + col] =
        __floats2bfloat162_rn(oacc[fn][0] * inv0, oacc[fn][1] * inv0);
    *(bf162*)&Og[(size_t)(row0 + 8) * CD + col] =
        __floats2bfloat162_rn(oacc[fn][2] * inv1, oacc[fn][3] * inv1);
  }
}

// ---------------------------------------------------------------------------
// Launch pipeline
// ---------------------------------------------------------------------------
extern "C" void kernel_launch(void* const* d_in, const int* in_sizes, int n_in,
                              void* d_out, int out_size) {
  const float* hidden = (const float*)d_in[0];
  const float* ln1 = (const float*)d_in[1];
  const float* ln2 = (const float*)d_in[2];
  const float* q_Us = (const float*)d_in[3];
  const float* q_V  = (const float*)d_in[4];
  const float* k_Us = (const float*)d_in[5];
  const float* k_V  = (const float*)d_in[6];
  const float* v_Us = (const float*)d_in[7];
  const float* v_V  = (const float*)d_in[8];
  const float* o_Us = (const float*)d_in[9];
  const float* o_V  = (const float*)d_in[10];
  const float* g_Us = (const float*)d_in[11];
  const float* g_V  = (const float*)d_in[12];
  const float* u_Us = (const float*)d_in[13];
  const float* u_V  = (const float*)d_in[14];
  const float* d_Us = (const float*)d_in[15];
  const float* d_V  = (const float*)d_in[16];
  float* out = (float*)d_out;

  Scratch* s = nullptr;
  cudaGetSymbolAddress((void**)&s, g_scratch);

  // 0. weight conversion + rope table
  {
    CvtPack p;
    const float* srcs[NCVT] = {q_V, k_V, v_V, o_Us, o_V, g_Us,
                               g_V, u_Us, u_V, d_Us, d_V};
    bf16* dsts[NCVT] = {s->qV, s->kV, s->vV, s->oUs, s->oV, s->gUs,
                        s->gV, s->uUs, s->uV, s->dUs, s->dV};
    const int ns[NCVT] = {1024 * CD, 256 * CD, 256 * CD, CD * 512, 512 * CD,
                          CINTER * 512, 512 * CD, CINTER * 512, 512 * CD,
                          CD * 512, 512 * CINTER};
    int total4 = 0;
    for (int i = 0; i < NCVT; i++) {
      p.src[i] = srcs[i]; p.dst[i] = dsts[i]; p.n4[i] = ns[i] / 4;
      total4 += ns[i] / 4;
    }
    cvt_f2bf<<<(total4 + 255) / 256, 256>>>(p, total4);
  }
  rope_tab<<<CT * 32 / 256, 256>>>(s->ropeC, s->ropeS);

  // 1. x = rmsnorm(hidden, ln1)
  rmsnorm_bf<<<CT, 256>>>(hidden, ln1, s->x);

  // 2. fused QKV low-rank projection
  gemm_bf<0><<<dim3(12, 16, 1), 256>>>(s->x, s->qV, nullptr, s->Pqkv,
                                       nullptr, nullptr, nullptr, nullptr,
                                       nullptr, 1536, CD);

  // 3. Us up-projections + RoPE
  proj_us_rope<<<dim3(CT / 32, CH), dim3(32, 8)>>>(
      s->Pqkv, q_Us, s->ropeC, s->ropeS, s->q, 1536, 1);
  proj_us_rope<<<dim3(CT / 32, CHK), dim3(32, 8)>>>(
      s->Pqkv + 1024, k_Us, s->ropeC, s->ropeS, s->k, 1536, 1);
  proj_us_rope<<<dim3(CT / 32, CHK), dim3(32, 8)>>>(
      s->Pqkv + 1280, v_Us, s->ropeC, s->ropeS, s->v, 1536, 0);

  // 4. attention
  flash_attn_bf<<<dim3(CT / 128, CH), 256>>>(s->q, s->k, s->v, s->attn);

  // 5. output projection (split-K=2) + residual -> h
  gemm_bf_sk<<<dim3(4, 16, 2), 256>>>(s->attn, s->oV, s->skpart, 512, CD,
                                      1024);
  reduce_sk<<<CT * 512 / 1024, 256>>>(s->skpart, s->Po, CT * 512, 2);
  gemm_bf<0><<<dim3(16, 16, 1), 256>>>(s->Po, s->oUs, hidden, s->h,
                                       nullptr, nullptr, nullptr, nullptr,
                                       nullptr, CD, 512);

  // 6. FFN
  rmsnorm_bf<<<CT, 256>>>(s->h, ln2, s->x);
  gemm_bf<1><<<dim3(4, 16, 2), 256>>>(s->x, s->gV, nullptr, s->Pg,
                                      s->x, s->uV, nullptr, s->Pu,
                                      nullptr, 512, CD);
  // gate = silu(Pg * gUs^T)
  gemm_bf<2><<<dim3(64, 16, 1), 256>>>(s->Pg, s->gUs, nullptr, s->gate,
                                       nullptr, nullptr, nullptr, nullptr,
                                       nullptr, CINTER, 512);
  // up = (Pu * uUs^T) * gate   (fused silu-mul)
  gemm_bf<3><<<dim3(64, 16, 1), 256>>>(s->Pu, s->uUs, nullptr, s->up,
                                       nullptr, nullptr, nullptr, nullptr,
                                       s->gate, CINTER, 512);
  gemm_bf_sk<<<dim3(4, 16, 4), 256>>>(s->up, s->dV, s->skpart, 512, CINTER,
                                      2048);
  reduce_sk<<<CT * 512 / 1024, 256>>>(s->skpart, s->Pd, CT * 512, 4);
  gemm_bf<0><<<dim3(16, 16, 1), 256>>>(s->Pd, s->dUs, s->h, out,
                                       nullptr, nullptr, nullptr, nullptr,
                                       nullptr, CD, 512);
}

// round 7
// speedup vs baseline: 8.4519x; 1.1005x over previous
#include <cuda_runtime.h>
#include <cuda_bf16.h>
#include <math.h>
#include <cstdint>

#define CT 2048
#define CD 2048
#define CH 32
#define CHK 8
#define CDH 64
#define CINTER 8192

typedef __nv_bfloat16 bf16;
typedef __nv_bfloat162 bf162;

// ---------------------------------------------------------------------------
// Static device scratch
// ---------------------------------------------------------------------------
struct alignas(256) Scratch {
  float Pqkv[CT * 1536];
  float h[CT * CD];
  float skpart[4 * CT * 512];
  float ropeC[CT * 32];
  float ropeS[CT * 32];
  bf16 x[CT * CD];
  bf16 q[CH * CT * CDH];
  bf16 k[CHK * CT * CDH];
  bf16 v[CHK * CT * CDH];
  bf16 attn[CT * CD];
  bf16 Po[CT * 512];
  bf16 Pg[CT * 512];
  bf16 Pu[CT * 512];
  bf16 gate[CT * CINTER];
  bf16 up[CT * CINTER];
  bf16 Pd[CT * 512];
  bf16 qV[1024 * CD];
  bf16 kV[256 * CD];
  bf16 vV[256 * CD];
  bf16 oUs[CD * 512];
  bf16 oV[512 * CD];
  bf16 gUs[CINTER * 512];
  bf16 gV[512 * CD];
  bf16 uUs[CINTER * 512];
  bf16 uV[512 * CD];
  bf16 dUs[CD * 512];
  bf16 dV[512 * CINTER];
};
__device__ Scratch g_scratch;

// ---------------------------------------------------------------------------
// helpers
// ---------------------------------------------------------------------------
__device__ __forceinline__ void cp16(void* s, const void* g) {
  uint32_t sa = (uint32_t)__cvta_generic_to_shared(s);
  asm volatile("cp.async.cg.shared.global [%0], [%1], 16;" ::"r"(sa), "l"(g));
}
__device__ __forceinline__ void mma_bf16(float* c, const uint32_t* a,
                                         const uint32_t* b) {
  asm volatile(
      "mma.sync.aligned.m16n8k16.row.col.f32.bf16.bf16.f32 "
      "{%0,%1,%2,%3}, {%4,%5,%6,%7}, {%8,%9}, {%0,%1,%2,%3};"
      : "+f"(c[0]), "+f"(c[1]), "+f"(c[2]), "+f"(c[3])
      : "r"(a[0]), "r"(a[1]), "r"(a[2]), "r"(a[3]), "r"(b[0]), "r"(b[1]));
}
__device__ __forceinline__ void ldm4(uint32_t* r, const void* p) {
  uint32_t a = (uint32_t)__cvta_generic_to_shared(p);
  asm volatile(
      "ldmatrix.sync.aligned.m8n8.x4.shared.b16 {%0,%1,%2,%3}, [%4];"
      : "=r"(r[0]), "=r"(r[1]), "=r"(r[2]), "=r"(r[3])
      : "r"(a));
}
__device__ __forceinline__ uint32_t packbf(float a, float b) {
  bf162 v = __floats2bfloat162_rn(a, b);
  return *(uint32_t*)&v;
}

// ---------------------------------------------------------------------------
// weight conversion fp32 -> bf16
// ---------------------------------------------------------------------------
#define NCVT 11
struct CvtPack {
  const float* src[NCVT];
  bf16* dst[NCVT];
  int n4[NCVT];
};
__global__ void cvt_f2bf(CvtPack p, int total4) {
  int i = blockIdx.x * 256 + threadIdx.x;
  if (i >= total4) return;
  int s = 0, off = i;
  while (off >= p.n4[s]) { off -= p.n4[s]; s++; }
  const float4 v = ((const float4*)p.src[s])[off];
  bf162* d = (bf162*)p.dst[s];
  d[off * 2] = __floats2bfloat162_rn(v.x, v.y);
  d[off * 2 + 1] = __floats2bfloat162_rn(v.z, v.w);
}

// rope cos/sin table
__global__ void rope_tab(float* __restrict__ c, float* __restrict__ s) {
  const int i = blockIdx.x * 256 + threadIdx.x;
  const int t = i >> 5, d = i & 31;
  const float invf = exp2f(-0.41524101186092028f * (float)d);
  float sn, cs;
  sincosf((float)t * invf, &sn, &cs);
  c[i] = cs;
  s[i] = sn;
}

// ---------------------------------------------------------------------------
// RMSNorm (fp32 in, bf16 out)
// ---------------------------------------------------------------------------
__global__ void rmsnorm_bf(const float* __restrict__ in,
                           const float* __restrict__ w,
                           bf16* __restrict__ out) {
  const int t = blockIdx.x;
  const float* row = in + (size_t)t * CD;
  float ss = 0.f;
  for (int i = threadIdx.x; i < CD; i += 256) {
    float v = row[i];
    ss += v * v;
  }
  __shared__ float red[8];
#pragma unroll
  for (int o = 16; o > 0; o >>= 1) ss += __shfl_xor_sync(0xffffffffu, ss, o);
  if ((threadIdx.x & 31) == 0) red[threadIdx.x >> 5] = ss;
  __syncthreads();
  if (threadIdx.x == 0) {
    float v = 0.f;
#pragma unroll
    for (int i = 0; i < 8; i++) v += red[i];
    red[0] = v;
  }
  __syncthreads();
  const float inv = rsqrtf(red[0] * (1.0f / CD) + 1e-5f);
  for (int i = threadIdx.x * 2; i < CD; i += 512) {
    bf162 o = __floats2bfloat162_rn(row[i] * inv * w[i],
                                    row[i + 1] * inv * w[i + 1]);
    *(bf162*)&out[(size_t)t * CD + i] = o;
  }
}

// ---------------------------------------------------------------------------
// bf16 GEMM (NT), 4-stage cp.async pipeline. 128x128x32 tiles, dyn smem.
// MODE 0: fp32 out (+res). 1: bf16 out. 2: bf16 silu(out). 3: bf16 out*aux.
// ---------------------------------------------------------------------------
#define GST 4
#define GTILE (128 * 40)
#define GSMEM (2 * GST * GTILE * 2)

template <int MODE>
__global__ __launch_bounds__(256, 2) void gemm_bf(
    const bf16* __restrict__ A1, const bf16* __restrict__ B1,
    const float* __restrict__ res1, void* __restrict__ C1,
    const bf16* __restrict__ A2, const bf16* __restrict__ B2,
    const float* __restrict__ res2, void* __restrict__ C2,
    const bf16* __restrict__ aux, int N, int K) {
  const bf16* A = blockIdx.z ? A2 : A1;
  const bf16* B = blockIdx.z ? B2 : B1;
  const float* res = blockIdx.z ? res2 : res1;
  void* C = blockIdx.z ? C2 : C1;

  extern __shared__ bf16 dynsm[];
  bf16* As = dynsm;
  bf16* Bs = dynsm + GST * GTILE;

  const int tid = threadIdx.x;
  const int lane = tid & 31, warp = tid >> 5;
  const int wm = (warp & 1) * 64, wn = (warp >> 1) * 32;
  const int bm = blockIdx.y * 128, bn = blockIdx.x * 128;
  const int gi = lane >> 2, ti = lane & 3;
  const int grow = tid >> 1;
  const int gcol = (tid & 1) * 16;

  float acc[4][4][4];
#pragma unroll
  for (int i = 0; i < 4; i++)
#pragma unroll
    for (int j = 0; j < 4; j++)
#pragma unroll
      for (int l = 0; l < 4; l++) acc[i][j][l] = 0.f;

  const int nt = K >> 5;
  const bf16* gA = &A[(size_t)(bm + grow) * K + gcol];
  const bf16* gB = &B[(size_t)(bn + grow) * K + gcol];
  const int soff = grow * 40 + gcol;

#pragma unroll
  for (int s = 0; s < GST - 1; s++) {
    const int k0 = s << 5;
    cp16(&As[s * GTILE + soff], gA + k0);
    cp16(&As[s * GTILE + soff + 8], gA + k0 + 8);
    cp16(&Bs[s * GTILE + soff], gB + k0);
    cp16(&Bs[s * GTILE + soff + 8], gB + k0 + 8);
    asm volatile("cp.async.commit_group;" ::: "memory");
  }

  const int arow = wm + (lane & 15);
  const int acol = (lane >> 4) * 8;
  const int g8 = lane >> 3;
  const int brow = wn + (g8 >> 1) * 8 + (lane & 7);
  const int bcol = (g8 & 1) * 8;

  for (int t = 0; t < nt; t++) {
    asm volatile("cp.async.wait_group %0;" ::"n"(GST - 2) : "memory");
    __syncthreads();
    const int pf = t + GST - 1;
    if (pf < nt) {
      const int st = pf & (GST - 1);
      const int k0 = pf << 5;
      cp16(&As[st * GTILE + soff], gA + k0);
      cp16(&As[st * GTILE + soff + 8], gA + k0 + 8);
      cp16(&Bs[st * GTILE + soff], gB + k0);
      cp16(&Bs[st * GTILE + soff + 8], gB + k0 + 8);
    }
    asm volatile("cp.async.commit_group;" ::: "memory");

    const int buf = t & (GST - 1);
    bf16* Ab = As + buf * GTILE;
    bf16* Bb = Bs + buf * GTILE;
#pragma unroll
    for (int ks = 0; ks < 2; ks++) {
      uint32_t a[4][4], b[2][4];
#pragma unroll
      for (int fm = 0; fm < 4; fm++)
        ldm4(a[fm], &Ab[(arow + fm * 16) * 40 + ks * 16 + acol]);
      ldm4(b[0], &Bb[brow * 40 + ks * 16 + bcol]);
      ldm4(b[1], &Bb[(brow + 16) * 40 + ks * 16 + bcol]);
#pragma unroll
      for (int fm = 0; fm < 4; fm++)
#pragma unroll
        for (int fn = 0; fn < 4; fn++)
          mma_bf16(acc[fm][fn], a[fm], &b[fn >> 1][(fn & 1) * 2]);
    }
  }

#pragma unroll
  for (int fm = 0; fm < 4; fm++) {
#pragma unroll
    for (int fn = 0; fn < 4; fn++) {
      const int r = bm + wm + fm * 16 + gi;
      const int c = bn + wn + fn * 8 + ti * 2;
      float v[4] = {acc[fm][fn][0], acc[fm][fn][1], acc[fm][fn][2],
                    acc[fm][fn][3]};
      if (MODE == 0) {
        float* Cf = (float*)C;
        if (res) {
          const float2 r0 = *(const float2*)&res[(size_t)r * N + c];
          const float2 r1 = *(const float2*)&res[(size_t)(r + 8) * N + c];
          v[0] += r0.x; v[1] += r0.y; v[2] += r1.x; v[3] += r1.y;
        }
        *(float2*)&Cf[(size_t)r * N + c] = make_float2(v[0], v[1]);
        *(float2*)&Cf[(size_t)(r + 8) * N + c] = make_float2(v[2], v[3]);
      } else {
        if (MODE == 2) {
#pragma unroll
          for (int l = 0; l < 4; l++) v[l] = v[l] / (1.f + __expf(-v[l]));
        }
        if (MODE == 3) {
          const bf162 a0 = *(const bf162*)&aux[(size_t)r * N + c];
          const bf162 a1 = *(const bf162*)&aux[(size_t)(r + 8) * N + c];
          v[0] *= __bfloat162float(a0.x); v[1] *= __bfloat162float(a0.y);
          v[2] *= __bfloat162float(a1.x); v[3] *= __bfloat162float(a1.y);
        }
        bf16* Cb = (bf16*)C;
        *(bf162*)&Cb[(size_t)r * N + c] = __floats2bfloat162_rn(v[0], v[1]);
        *(bf162*)&Cb[(size_t)(r + 8) * N + c] =
            __floats2bfloat162_rn(v[2], v[3]);
      }
    }
  }
}

// ---------------------------------------------------------------------------
// split-K bf16 GEMM (4-stage) + reducer
// ---------------------------------------------------------------------------
__global__ __launch_bounds__(256, 2) void gemm_bf_sk(
    const bf16* __restrict__ A, const bf16* __restrict__ B,
    float* __restrict__ Cpart, int N, int K, int Kc) {
  extern __shared__ bf16 dynsm[];
  bf16* As = dynsm;
  bf16* Bs = dynsm + GST * GTILE;

  const int tid = threadIdx.x;
  const int lane = tid & 31, warp = tid >> 5;
  const int wm = (warp & 1) * 64, wn = (warp >> 1) * 32;
  const int bm = blockIdx.y * 128, bn = blockIdx.x * 128;
  const int gi = lane >> 2, ti = lane & 3;
  const int grow = tid >> 1;
  const int gcol = (tid & 1) * 16;
  const int kbase = blockIdx.z * Kc;
  float* C = Cpart + (size_t)blockIdx.z * CT * N;

  float acc[4][4][4];
#pragma unroll
  for (int i = 0; i < 4; i++)
#pragma unroll
    for (int j = 0; j < 4; j++)
#pragma unroll
      for (int l = 0; l < 4; l++) acc[i][j][l] = 0.f;

  const int nt = Kc >> 5;
  const bf16* gA = &A[(size_t)(bm + grow) * K + kbase + gcol];
  const bf16* gB = &B[(size_t)(bn + grow) * K + kbase + gcol];
  const int soff = grow * 40 + gcol;

#pragma unroll
  for (int s = 0; s < GST - 1; s++) {
    const int k0 = s << 5;
    cp16(&As[s * GTILE + soff], gA + k0);
    cp16(&As[s * GTILE + soff + 8], gA + k0 + 8);
    cp16(&Bs[s * GTILE + soff], gB + k0);
    cp16(&Bs[s * GTILE + soff + 8], gB + k0 + 8);
    asm volatile("cp.async.commit_group;" ::: "memory");
  }

  const int arow = wm + (lane & 15);
  const int acol = (lane >> 4) * 8;
  const int g8 = lane >> 3;
  const int brow = wn + (g8 >> 1) * 8 + (lane & 7);
  const int bcol = (g8 & 1) * 8;

  for (int t = 0; t < nt; t++) {
    asm volatile("cp.async.wait_group %0;" ::"n"(GST - 2) : "memory");
    __syncthreads();
    const int pf = t + GST - 1;
    if (pf < nt) {
      const int st = pf & (GST - 1);
      const int k0 = pf << 5;
      cp16(&As[st * GTILE + soff], gA + k0);
      cp16(&As[st * GTILE + soff + 8], gA + k0 + 8);
      cp16(&Bs[st * GTILE + soff], gB + k0);
      cp16(&Bs[st * GTILE + soff + 8], gB + k0 + 8);
    }
    asm volatile("cp.async.commit_group;" ::: "memory");

    const int buf = t & (GST - 1);
    bf16* Ab = As + buf * GTILE;
    bf16* Bb = Bs + buf * GTILE;
#pragma unroll
    for (int ks = 0; ks < 2; ks++) {
      uint32_t a[4][4], b[2][4];
#pragma unroll
      for (int fm = 0; fm < 4; fm++)
        ldm4(a[fm], &Ab[(arow + fm * 16) * 40 + ks * 16 + acol]);
      ldm4(b[0], &Bb[brow * 40 + ks * 16 + bcol]);
      ldm4(b[1], &Bb[(brow + 16) * 40 + ks * 16 + bcol]);
#pragma unroll
      for (int fm = 0; fm < 4; fm++)
#pragma unroll
        for (int fn = 0; fn < 4; fn++)
          mma_bf16(acc[fm][fn], a[fm], &b[fn >> 1][(fn & 1) * 2]);
    }
  }

#pragma unroll
  for (int fm = 0; fm < 4; fm++) {
#pragma unroll
    for (int fn = 0; fn < 4; fn++) {
      const int r = bm + wm + fm * 16 + gi;
      const int c = bn + wn + fn * 8 + ti * 2;
      *(float2*)&C[(size_t)r * N + c] =
          make_float2(acc[fm][fn][0], acc[fm][fn][1]);
      *(float2*)&C[(size_t)(r + 8) * N + c] =
          make_float2(acc[fm][fn][2], acc[fm][fn][3]);
    }
  }
}

__global__ void reduce_sk(const float* __restrict__ part,
                          bf16* __restrict__ out, int MN, int S) {
  const int i = (blockIdx.x * 256 + threadIdx.x) * 4;
  if (i >= MN) return;
  float4 a = *(const float4*)&part[i];
  for (int s = 1; s < S; s++) {
    const float4 p = *(const float4*)&part[(size_t)s * MN + i];
    a.x += p.x; a.y += p.y; a.z += p.z; a.w += p.w;
  }
  *(bf162*)&out[i] = __floats2bfloat162_rn(a.x, a.y);
  *(bf162*)&out[i + 2] = __floats2bfloat162_rn(a.z, a.w);
}

// ---------------------------------------------------------------------------
// Per-head Us projection + optional RoPE (from table). fp32 in, bf16 out.
// ---------------------------------------------------------------------------
__global__ void proj_us_rope(const float* __restrict__ P,
                             const float* __restrict__ Us,
                             const float* __restrict__ tC,
                             const float* __restrict__ tS,
                             bf16* __restrict__ out, int pstride, int doRope) {
  const int hh = blockIdx.y;
  const int tg = threadIdx.y;
  const int dh = threadIdx.x;
  const int t0 = blockIdx.x * 32 + tg * 4;
  __shared__ float sUs[64][33];
  __shared__ float sP[32][33];
  const int tid = tg * 32 + dh;
  const float* UsH = Us + (size_t)hh * 64 * 32;
#pragma unroll
  for (int i = tid; i < 64 * 32; i += 256) sUs[i >> 5][i & 31] = UsH[i];
#pragma unroll
  for (int j = 0; j < 4; j++)
    sP[tg * 4 + j][dh] = P[(size_t)(t0 + j) * pstride + hh * 32 + dh];
  __syncthreads();
  float x1[4] = {0.f, 0.f, 0.f, 0.f}, x2[4] = {0.f, 0.f, 0.f, 0.f};
#pragma unroll
  for (int r = 0; r < 32; r++) {
    const float u1 = sUs[dh][r];
    const float u2 = sUs[dh + 32][r];
#pragma unroll
    for (int j = 0; j < 4; j++) {
      const float p = sP[tg * 4 + j][r];
      x1[j] = fmaf(p, u1, x1[j]);
      x2[j] = fmaf(p, u2, x2[j]);
    }
  }
#pragma unroll
  for (int j = 0; j < 4; j++) {
    float o1 = x1[j], o2 = x2[j];
    if (doRope) {
      const float cs = tC[(t0 + j) * 32 + dh];
      const float sn = tS[(t0 + j) * 32 + dh];
      o1 = x1[j] * cs - x2[j] * sn;
      o2 = x2[j] * cs + x1[j] * sn;
    }
    const size_t base = ((size_t)hh * CT + t0 + j) * CDH;
    out[base + dh] = __float2bfloat16(o1);
    out[base + dh + 32] = __float2bfloat16(o2);
  }
}

// ---------------------------------------------------------------------------
// bf16 causal flash attention, FA2-style. Q tile 128 rows, 8 warps x 16 rows.
// ---------------------------------------------------------------------------
#define FTS2 72
__global__ __launch_bounds__(256) void flash_attn_bf(
    const bf16* __restrict__ Q, const bf16* __restrict__ Kg,
    const bf16* __restrict__ Vg, bf16* __restrict__ Og) {
  __shared__ bf16 Qs[128 * FTS2];
  __shared__ bf16 Ks[64 * FTS2];
  __shared__ bf16 Vt[64 * FTS2];

  const int qb = blockIdx.x, hh = blockIdx.y, hk = hh >> 2;
  const int tid = threadIdx.x;
  const int lane = tid & 31, warp = tid >> 5;
  const int gi = lane >> 2, ti = lane & 3;
  const int wm = warp * 16;
  const int ldr = tid >> 3, c8 = (tid & 7) * 8;

#pragma unroll
  for (int r = 0; r < 4; r++) {
    const int row = ldr + r * 32;
    *(float4*)&Qs[row * FTS2 + c8] =
        *(const float4*)&Q[((size_t)hh * CT + qb * 128 + row) * 64 + c8];
  }
  __syncthreads();

  const int arow_ = wm + (lane & 15);
  const int acol = (lane >> 4) * 8;
  uint32_t aq[4][4];
#pragma unroll
  for (int ks = 0; ks < 4; ks++)
    ldm4(aq[ks], &Qs[arow_ * FTS2 + ks * 16 + acol]);

  const int g8 = lane >> 3;
  const int nbrow = (g8 >> 1) * 8 + (lane & 7);
  const int bcol = (g8 & 1) * 8;

  float m0 = -1e30f, m1 = -1e30f, l0 = 0.f, l1 = 0.f;
  float oacc[8][4];
#pragma unroll
  for (int i = 0; i < 8; i++)
#pragma unroll
    for (int j = 0; j < 4; j++) oacc[i][j] = 0.f;

  const int row0 = qb * 128 + wm + gi;
  const int kbmax = 2 * qb + 1;

  for (int kb = 0; kb <= kbmax; kb++) {
    __syncthreads();
#pragma unroll
    for (int r = 0; r < 2; r++) {
      const int row = ldr + r * 32;
      const size_t gbase = ((size_t)hk * CT + kb * 64 + row) * 64 + c8;
      *(float4*)&Ks[row * FTS2 + c8] = *(const float4*)&Kg[gbase];
      const uint4 vv = *(const uint4*)&Vg[gbase];
      const bf16* pv = (const bf16*)&vv;
#pragma unroll
      for (int j = 0; j < 8; j++) Vt[(c8 + j) * FTS2 + row] = pv[j];
    }
    __syncthreads();

    float sacc[8][4];
#pragma unroll
    for (int i = 0; i < 8; i++)
#pragma unroll
      for (int j = 0; j < 4; j++) sacc[i][j] = 0.f;
#pragma unroll
    for (int ks = 0; ks < 4; ks++) {
      uint32_t b[4][4];
#pragma unroll
      for (int nb = 0; nb < 4; nb++)
        ldm4(b[nb], &Ks[(nbrow + nb * 16) * FTS2 + ks * 16 + bcol]);
#pragma unroll
      for (int fn = 0; fn < 8; fn++)
        mma_bf16(sacc[fn], aq[ks], &b[fn >> 1][(fn & 1) * 2]);
    }

    const bool needMask = (kb * 64 + 63) > row0;
    float rmax0 = -1e30f, rmax1 = -1e30f;
#pragma unroll
    for (int fn = 0; fn < 8; fn++) {
      const int c = kb * 64 + fn * 8 + 2 * ti;
#pragma unroll
      for (int l = 0; l < 4; l++) {
        float v = sacc[fn][l] * 0.125f;
        if (needMask) {
          const int row = row0 + ((l >= 2) ? 8 : 0);
          if (c + (l & 1) > row) v = -1e30f;
        }
        sacc[fn][l] = v;
        if (l >= 2) rmax1 = fmaxf(rmax1, v);
        else rmax0 = fmaxf(rmax0, v);
      }
    }
    rmax0 = fmaxf(rmax0, __shfl_xor_sync(0xffffffffu, rmax0, 1));
    rmax0 = fmaxf(rmax0, __shfl_xor_sync(0xffffffffu, rmax0, 2));
    rmax1 = fmaxf(rmax1, __shfl_xor_sync(0xffffffffu, rmax1, 1));
    rmax1 = fmaxf(rmax1, __shfl_xor_sync(0xffffffffu, rmax1, 2));
    const float mn0 = fmaxf(m0, rmax0), mn1 = fmaxf(m1, rmax1);
    const float al0 = __expf(m0 - mn0), al1 = __expf(m1 - mn1);
    m0 = mn0; m1 = mn1;

    float rs0 = 0.f, rs1 = 0.f;
    uint32_t ap[4][4];
#pragma unroll
    for (int ks = 0; ks < 4; ks++) {
      const int f0 = 2 * ks, f1 = 2 * ks + 1;
      const float p00 = __expf(sacc[f0][0] - m0);
      const float p01 = __expf(sacc[f0][1] - m0);
      const float p02 = __expf(sacc[f0][2] - m1);
      const float p03 = __expf(sacc[f0][3] - m1);
      const float p10 = __expf(sacc[f1][0] - m0);
      const float p11 = __expf(sacc[f1][1] - m0);
      const float p12 = __expf(sacc[f1][2] - m1);
      const float p13 = __expf(sacc[f1][3] - m1);
      rs0 += p00 + p01 + p10 + p11;
      rs1 += p02 + p03 + p12 + p13;
      ap[ks][0] = packbf(p00, p01);
      ap[ks][1] = packbf(p02, p03);
      ap[ks][2] = packbf(p10, p11);
      ap[ks][3] = packbf(p12, p13);
    }
    rs0 += __shfl_xor_sync(0xffffffffu, rs0, 1);
    rs0 += __shfl_xor_sync(0xffffffffu, rs0, 2);
    rs1 += __shfl_xor_sync(0xffffffffu, rs1, 1);
    rs1 += __shfl_xor_sync(0xffffffffu, rs1, 2);
    l0 = l0 * al0 + rs0;
    l1 = l1 * al1 + rs1;
#pragma unroll
    for (int fn = 0; fn < 8; fn++) {
      oacc[fn][0] *= al0; oacc[fn][1] *= al0;
      oacc[fn][2] *= al1; oacc[fn][3] *= al1;
    }

#pragma unroll
    for (int ks = 0; ks < 4; ks++) {
      uint32_t b[4][4];
#pragma unroll
      for (int nb = 0; nb < 4; nb++)
        ldm4(b[nb], &Vt[(nbrow + nb * 16) * FTS2 + ks * 16 + bcol]);
#pragma unroll
      for (int fn = 0; fn < 8; fn++)
        mma_bf16(oacc[fn], ap[ks], &b[fn >> 1][(fn & 1) * 2]);
    }
  }

  const float inv0 = 1.f / l0, inv1 = 1.f / l1;
#pragma unroll
  for (int fn = 0; fn < 8; fn++) {
    const int col = hh * 64 + fn * 8 + 2 * ti;
    *(bf162*)&Og[(size_t)(row0) * CD + col] =
        __floats2bfloat162_rn(oacc[fn][0] * inv0, oacc[fn][1] * inv0);
    *(bf162*)&Og[(size_t)(row0 + 8) * CD + col] =
        __floats2bfloat162_rn(oacc[fn][2] * inv1, oacc[fn][3] * inv1);
  }
}

// ---------------------------------------------------------------------------
// Launch pipeline
// ---------------------------------------------------------------------------
extern "C" void kernel_launch(void* const* d_in, const int* in_sizes, int n_in,
                              void* d_out, int out_size) {
  const float* hidden = (const float*)d_in[0];
  const float* ln1 = (const float*)d_in[1];
  const float* ln2 = (const float*)d_in[2];
  const float* q_Us = (const float*)d_in[3];
  const float* q_V  = (const float*)d_in[4];
  const float* k_Us = (const float*)d_in[5];
  const float* k_V  = (const float*)d_in[6];
  const float* v_Us = (const float*)d_in[7];
  const float* v_V  = (const float*)d_in[8];
  const float* o_Us = (const float*)d_in[9];
  const float* o_V  = (const float*)d_in[10];
  const float* g_Us = (const float*)d_in[11];
  const float* g_V  = (const float*)d_in[12];
  const float* u_Us = (const float*)d_in[13];
  const float* u_V  = (const float*)d_in[14];
  const float* d_Us = (const float*)d_in[15];
  const float* d_V  = (const float*)d_in[16];
  float* out = (float*)d_out;

  Scratch* s = nullptr;
  cudaGetSymbolAddress((void**)&s, g_scratch);

  cudaFuncSetAttribute(gemm_bf<0>,
                       cudaFuncAttributeMaxDynamicSharedMemorySize, GSMEM);
  cudaFuncSetAttribute(gemm_bf<1>,
                       cudaFuncAttributeMaxDynamicSharedMemorySize, GSMEM);
  cudaFuncSetAttribute(gemm_bf<2>,
                       cudaFuncAttributeMaxDynamicSharedMemorySize, GSMEM);
  cudaFuncSetAttribute(gemm_bf<3>,
                       cudaFuncAttributeMaxDynamicSharedMemorySize, GSMEM);
  cudaFuncSetAttribute(gemm_bf_sk,
                       cudaFuncAttributeMaxDynamicSharedMemorySize, GSMEM);

  // 0. weight conversion + rope table
  {
    CvtPack p;
    const float* srcs[NCVT] = {q_V, k_V, v_V, o_Us, o_V, g_Us,
                               g_V, u_Us, u_V, d_Us, d_V};
    bf16* dsts[NCVT] = {s->qV, s->kV, s->vV, s->oUs, s->oV, s->gUs,
                        s->gV, s->uUs, s->uV, s->dUs, s->dV};
    const int ns[NCVT] = {1024 * CD, 256 * CD, 256 * CD, CD * 512, 512 * CD,
                          CINTER * 512, 512 * CD, CINTER * 512, 512 * CD,
                          CD * 512, 512 * CINTER};
    int total4 = 0;
    for (int i = 0; i < NCVT; i++) {
      p.src[i] = srcs[i]; p.dst[i] = dsts[i]; p.n4[i] = ns[i] / 4;
      total4 += ns[i] / 4;
    }
    cvt_f2bf<<<(total4 + 255) / 256, 256>>>(p, total4);
  }
  rope_tab<<<CT * 32 / 256, 256>>>(s->ropeC, s->ropeS);

  // 1. x = rmsnorm(hidden, ln1)
  rmsnorm_bf<<<CT, 256>>>(hidden, ln1, s->x);

  // 2. fused QKV low-rank projection
  gemm_bf<0><<<dim3(12, 16, 1), 256, GSMEM>>>(
      s->x, s->qV, nullptr, s->Pqkv, nullptr, nullptr, nullptr, nullptr,
      nullptr, 1536, CD);

  // 3. Us up-projections + RoPE
  proj_us_rope<<<dim3(CT / 32, CH), dim3(32, 8)>>>(
      s->Pqkv, q_Us, s->ropeC, s->ropeS, s->q, 1536, 1);
  proj_us_rope<<<dim3(CT / 32, CHK), dim3(32, 8)>>>(
      s->Pqkv + 1024, k_Us, s->ropeC, s->ropeS, s->k, 1536, 1);
  proj_us_rope<<<dim3(CT / 32, CHK), dim3(32, 8)>>>(
      s->Pqkv + 1280, v_Us, s->ropeC, s->ropeS, s->v, 1536, 0);

  // 4. attention
  flash_attn_bf<<<dim3(CT / 128, CH), 256>>>(s->q, s->k, s->v, s->attn);

  // 5. output projection (split-K=2) + residual -> h
  gemm_bf_sk<<<dim3(4, 16, 2), 256, GSMEM>>>(s->attn, s->oV, s->skpart, 512,
                                             CD, 1024);
  reduce_sk<<<CT * 512 / 1024, 256>>>(s->skpart, s->Po, CT * 512, 2);
  gemm_bf<0><<<dim3(16, 16, 1), 256, GSMEM>>>(
      s->Po, s->oUs, hidden, s->h, nullptr, nullptr, nullptr, nullptr,
      nullptr, CD, 512);

  // 6. FFN
  rmsnorm_bf<<<CT, 256>>>(s->h, ln2, s->x);
  gemm_bf<1><<<dim3(4, 16, 2), 256, GSMEM>>>(
      s->x, s->gV, nullptr, s->Pg, s->x, s->uV, nullptr, s->Pu,
      nullptr, 512, CD);
  gemm_bf<2><<<dim3(64, 16, 1), 256, GSMEM>>>(
      s->Pg, s->gUs, nullptr, s->gate, nullptr, nullptr, nullptr, nullptr,
      nullptr, CINTER, 512);
  gemm_bf<3><<<dim3(64, 16, 1), 256, GSMEM>>>(
      s->Pu, s->uUs, nullptr, s->up, nullptr, nullptr, nullptr, nullptr,
      s->gate, CINTER, 512);
  gemm_bf_sk<<<dim3(4, 16, 4), 256, GSMEM>>>(s->up, s->dV, s->skpart, 512,
                                             CINTER, 2048);
  reduce_sk<<<CT * 512 / 1024, 256>>>(s->skpart, s->Pd, CT * 512, 4);
  gemm_bf<0><<<dim3(16, 16, 1), 256, GSMEM>>>(
      s->Pd, s->dUs, s->h, out, nullptr, nullptr, nullptr, nullptr,
      nullptr, CD, 512);
}